// round 1
// baseline (speedup 1.0000x reference)
#include <cuda_runtime.h>

// Problem constants (fixed shapes)
#define BATCH 4
#define H 256
#define W 256
#define C0 32
#define C 64
#define HT 513   // conv_transpose output spatial: (256-1)*2+3
#define HO 511   // final VALID conv output: 513-2

// ---------------------------------------------------------------------------
// Scratch buffers (static device allocations; no cudaMalloc allowed)
// ---------------------------------------------------------------------------
__device__ float g_x0[BATCH * H * W * C0];       //  33.5 MB
__device__ float g_mask0[BATCH * H * W];         //   1.0 MB
__device__ float g_mask1[BATCH * H * W];         //   1.0 MB
__device__ float g_mask4[BATCH * HT * HT];       //   4.2 MB
__device__ float g_h1[BATCH * H * W * C];        //  67.1 MB
__device__ float g_h2[BATCH * H * W * C];        //  67.1 MB
__device__ float g_ht[BATCH * HT * HT * C];      // 269.5 MB

// ---------------------------------------------------------------------------
// Zero the scatter targets (must re-zero every replay; graph-captured)
// ---------------------------------------------------------------------------
__global__ void zero_kernel() {
    int i = blockIdx.x * blockDim.x + threadIdx.x;
    if (i < BATCH * H * W * C0 / 4)
        reinterpret_cast<float4*>(g_x0)[i] = make_float4(0.f, 0.f, 0.f, 0.f);
    if (i < BATCH * H * W / 4)
        reinterpret_cast<float4*>(g_mask0)[i] = make_float4(0.f, 0.f, 0.f, 0.f);
}

// ---------------------------------------------------------------------------
// Scatter-add features into dense grid + presence mask
// 32 threads per point (one per channel)
// ---------------------------------------------------------------------------
__global__ void scatter_kernel(const float* __restrict__ feat,
                               const int* __restrict__ coors, int n) {
    int t = blockIdx.x * blockDim.x + threadIdx.x;
    int p = t >> 5;
    int c = t & 31;
    if (p >= n) return;
    int b = coors[3 * p + 0];
    int y = coors[3 * p + 1];
    int x = coors[3 * p + 2];
    int pix = (b * H + y) * W + x;
    atomicAdd(&g_x0[pix * C0 + c], feat[p * C0 + c]);
    if (c == 0) g_mask0[pix] = 1.0f;
}

// mask1 = 3x3 dilation of mask0 (SAME, zero pad)
__global__ void mask1_kernel() {
    int i = blockIdx.x * blockDim.x + threadIdx.x;
    if (i >= BATCH * H * W) return;
    int x = i % W;
    int y = (i / W) % H;
    int b = i / (H * W);
    float m = 0.f;
#pragma unroll
    for (int dy = -1; dy <= 1; dy++)
#pragma unroll
        for (int dx = -1; dx <= 1; dx++) {
            int yy = y + dy, xx = x + dx;
            if (yy >= 0 && yy < H && xx >= 0 && xx < W)
                m = fmaxf(m, g_mask0[(b * H + yy) * W + xx]);
        }
    g_mask1[i] = (m > 0.f) ? 1.f : 0.f;
}

// mask4 = (conv_transpose(mask1, ones3, stride 2, VALID) > 0)
// out(oy,ox) uses input (iy,ix) with oy+ky-2 = 2*iy (ky in 0..2), same for x.
__global__ void mask4_kernel() {
    int i = blockIdx.x * blockDim.x + threadIdx.x;
    if (i >= BATCH * HT * HT) return;
    int ox = i % HT;
    int oy = (i / HT) % HT;
    int b = i / (HT * HT);
    float m = 0.f;
#pragma unroll
    for (int ky = 0; ky < 3; ky++) {
        int t = oy + ky - 2;
        if (t & 1) continue;
        int iy = t >> 1;
        if (iy < 0 || iy >= H) continue;
#pragma unroll
        for (int kx = 0; kx < 3; kx++) {
            int s = ox + kx - 2;
            if (s & 1) continue;
            int ix = s >> 1;
            if (ix < 0 || ix >= W) continue;
            m = fmaxf(m, g_mask1[(b * H + iy) * W + ix]);
        }
    }
    g_mask4[i] = (m > 0.f) ? 1.f : 0.f;
}

// ---------------------------------------------------------------------------
// Direct 3x3 conv, NHWC, Cout=64.
// Block: 128 threads = (16 co-quads) x (8 rows). Tile: 8x8 output pixels.
// Each thread: 8 pixels x 4 channels = 8 float4 accumulators.
// Input tile in smem (+4 float row pad to avoid bank conflicts),
// weights streamed from gmem (L1/L2-hot, coalesced float4 across tx).
// out = relu((conv + bias) [* mask])
// ---------------------------------------------------------------------------
template <int CIN, bool MASK>
__global__ __launch_bounds__(128)
void conv3x3_kernel(const float* __restrict__ in, const float* __restrict__ w,
                    const float* __restrict__ bias, const float* __restrict__ mask,
                    float* __restrict__ out,
                    int IH, int IW, int OH, int OW, int pad) {
    constexpr int ROWF = 10 * CIN + 4;   // padded smem row stride (floats)
    __shared__ float smem[10 * ROWF];

    const int tx = threadIdx.x;          // 0..15 -> co = 4*tx
    const int ty = threadIdx.y;          // 0..7  -> output row in tile
    const int tid = ty * 16 + tx;
    const int oy0 = blockIdx.y * 8, ox0 = blockIdx.x * 8;
    const int b = blockIdx.z;
    const int iy0 = oy0 - pad, ix0 = ox0 - pad;
    const float* inb = in + (size_t)b * IH * IW * CIN;

    // cooperative load of (10 x 10 x CIN) input tile, zero-padded OOB
    for (int i = tid; i < 10 * 10 * (CIN / 4); i += 128) {
        int ci4 = i % (CIN / 4);
        int pix = i / (CIN / 4);
        int r = pix / 10, cc = pix % 10;
        int iy = iy0 + r, ix = ix0 + cc;
        float4 v = make_float4(0.f, 0.f, 0.f, 0.f);
        if (iy >= 0 && iy < IH && ix >= 0 && ix < IW)
            v = *reinterpret_cast<const float4*>(inb + ((size_t)iy * IW + ix) * CIN + 4 * ci4);
        *reinterpret_cast<float4*>(&smem[r * ROWF + cc * CIN + 4 * ci4]) = v;
    }
    __syncthreads();

    float4 acc[8];
#pragma unroll
    for (int p = 0; p < 8; p++) acc[p] = make_float4(0.f, 0.f, 0.f, 0.f);

#pragma unroll 1
    for (int k = 0; k < 9; k++) {
        int ky = k / 3;
        int kx = k - ky * 3;
        const float* wp = w + (size_t)k * CIN * 64 + 4 * tx;
        const float* sp = &smem[(ty + ky) * ROWF + kx * CIN];
#pragma unroll 8
        for (int ci = 0; ci < CIN; ci++) {
            float4 wv = *reinterpret_cast<const float4*>(wp + ci * 64);
#pragma unroll
            for (int p = 0; p < 8; p++) {
                float iv = sp[p * CIN + ci];
                acc[p].x = fmaf(iv, wv.x, acc[p].x);
                acc[p].y = fmaf(iv, wv.y, acc[p].y);
                acc[p].z = fmaf(iv, wv.z, acc[p].z);
                acc[p].w = fmaf(iv, wv.w, acc[p].w);
            }
        }
    }

    float4 bv = *reinterpret_cast<const float4*>(bias + 4 * tx);
    int oy = oy0 + ty;
    if (oy < OH) {
#pragma unroll
        for (int p = 0; p < 8; p++) {
            int ox = ox0 + p;
            if (ox < OW) {
                float4 v;
                v.x = acc[p].x + bv.x;
                v.y = acc[p].y + bv.y;
                v.z = acc[p].z + bv.z;
                v.w = acc[p].w + bv.w;
                if (MASK) {
                    float m = mask[((size_t)b * OH + oy) * OW + ox];
                    v.x *= m; v.y *= m; v.z *= m; v.w *= m;
                }
                v.x = fmaxf(v.x, 0.f);
                v.y = fmaxf(v.y, 0.f);
                v.z = fmaxf(v.z, 0.f);
                v.w = fmaxf(v.w, 0.f);
                *reinterpret_cast<float4*>(out + (((size_t)b * OH + oy) * OW + ox) * 64 + 4 * tx) = v;
            }
        }
    }
}

// ---------------------------------------------------------------------------
// conv_transpose 3x3 stride 2 VALID (kernel NOT flipped, JAX semantics):
// out(oy,ox,co) = sum over (ky,kx,ci) with oy+ky-2 = 2*iy, ox+kx-2 = 2*ix of
//                 in(iy,ix,ci) * w[ky,kx,ci,co]
// then relu((. + bias) * mask4).
// Block: 128 threads = 16 co-quads x 8 rows; tile 8x8 outputs (513x513 grid).
// Needed input patch is 5x5 -> load 6x6x64 into smem.
// For a tile origin (oy0,ox0) both even: iy_local = (ty+ky)/2, ix_local = (px+kx)/2.
// ---------------------------------------------------------------------------
__global__ __launch_bounds__(128)
void convT_kernel(const float* __restrict__ in, const float* __restrict__ w,
                  const float* __restrict__ bias, const float* __restrict__ mask,
                  float* __restrict__ out) {
    constexpr int IST = 6 * 64 + 4;  // padded smem row stride
    __shared__ float smem[6 * IST];

    const int tx = threadIdx.x;  // co quad
    const int ty = threadIdx.y;  // output row in tile
    const int tid = ty * 16 + tx;
    const int oy0 = blockIdx.y * 8, ox0 = blockIdx.x * 8;
    const int b = blockIdx.z;
    const int iyb = oy0 / 2 - 1, ixb = ox0 / 2 - 1;
    const float* inb = in + (size_t)b * H * W * 64;

    for (int i = tid; i < 6 * 6 * 16; i += 128) {
        int ci4 = i & 15;
        int pix = i >> 4;
        int r = pix / 6, cc = pix % 6;
        int iy = iyb + r, ix = ixb + cc;
        float4 v = make_float4(0.f, 0.f, 0.f, 0.f);
        if (iy >= 0 && iy < H && ix >= 0 && ix < W)
            v = *reinterpret_cast<const float4*>(inb + ((size_t)iy * W + ix) * 64 + 4 * ci4);
        *reinterpret_cast<float4*>(&smem[r * IST + cc * 64 + 4 * ci4]) = v;
    }
    __syncthreads();

    float4 acc[8];
#pragma unroll
    for (int p = 0; p < 8; p++) acc[p] = make_float4(0.f, 0.f, 0.f, 0.f);

    const int oy = oy0 + ty;

#pragma unroll 1
    for (int ky = 0; ky < 3; ky++) {
        if ((ty + ky) & 1) continue;         // parity gate on rows
        const float* srow = &smem[((ty + ky) >> 1) * IST];
#pragma unroll
        for (int kx = 0; kx < 3; kx++) {
            const float* wp = w + (size_t)(ky * 3 + kx) * 64 * 64 + 4 * tx;
            constexpr int unused = 0; (void)unused;
            const int p0 = kx & 1;           // compile-time (kx unrolled)
            const int col0 = (p0 + kx) >> 1;
#pragma unroll 8
            for (int ci = 0; ci < 64; ci++) {
                float4 wv = *reinterpret_cast<const float4*>(wp + ci * 64);
#pragma unroll
                for (int j = 0; j < 4; j++) {
                    float iv = srow[(col0 + j) * 64 + ci];
                    int p = p0 + 2 * j;
                    acc[p].x = fmaf(iv, wv.x, acc[p].x);
                    acc[p].y = fmaf(iv, wv.y, acc[p].y);
                    acc[p].z = fmaf(iv, wv.z, acc[p].z);
                    acc[p].w = fmaf(iv, wv.w, acc[p].w);
                }
            }
        }
    }

    float4 bv = *reinterpret_cast<const float4*>(bias + 4 * tx);
    if (oy < HT) {
#pragma unroll
        for (int p = 0; p < 8; p++) {
            int ox = ox0 + p;
            if (ox < HT) {
                float m = mask[((size_t)b * HT + oy) * HT + ox];
                float4 v;
                v.x = fmaxf((acc[p].x + bv.x) * m, 0.f);
                v.y = fmaxf((acc[p].y + bv.y) * m, 0.f);
                v.z = fmaxf((acc[p].z + bv.z) * m, 0.f);
                v.w = fmaxf((acc[p].w + bv.w) * m, 0.f);
                *reinterpret_cast<float4*>(out + (((size_t)b * HT + oy) * HT + ox) * 64 + 4 * tx) = v;
            }
        }
    }
}

// ---------------------------------------------------------------------------
// Launch
// ---------------------------------------------------------------------------
extern "C" void kernel_launch(void* const* d_in, const int* in_sizes, int n_in,
                              void* d_out, int out_size) {
    const float* features = (const float*)d_in[0];
    const int* coors      = (const int*)d_in[1];
    // d_in[2] = batch_size (known: 4)
    const float* w1 = (const float*)d_in[3];
    const float* b1 = (const float*)d_in[4];
    const float* w2 = (const float*)d_in[5];
    const float* b2 = (const float*)d_in[6];
    const float* w3 = (const float*)d_in[7];
    const float* b3 = (const float*)d_in[8];
    const float* wt = (const float*)d_in[9];
    const float* bt = (const float*)d_in[10];
    const float* w5 = (const float*)d_in[11];
    const float* b5 = (const float*)d_in[12];
    float* out = (float*)d_out;

    const int N = in_sizes[0] / C0;

    float *x0, *m1, *m4, *h1, *h2, *ht;
    cudaGetSymbolAddress((void**)&x0, g_x0);
    cudaGetSymbolAddress((void**)&m1, g_mask1);
    cudaGetSymbolAddress((void**)&m4, g_mask4);
    cudaGetSymbolAddress((void**)&h1, g_h1);
    cudaGetSymbolAddress((void**)&h2, g_h2);
    cudaGetSymbolAddress((void**)&ht, g_ht);

    // 1. zero scatter targets
    {
        int n4 = BATCH * H * W * C0 / 4;
        zero_kernel<<<(n4 + 255) / 256, 256>>>();
    }
    // 2. scatter
    scatter_kernel<<<(N * 32 + 255) / 256, 256>>>(features, coors, N);
    // 3. mask1 dilation
    mask1_kernel<<<(BATCH * H * W + 255) / 256, 256>>>();
    // 4-6. masked convs
    {
        dim3 grid(W / 8, H / 8, BATCH), blk(16, 8);
        conv3x3_kernel<C0, true><<<grid, blk>>>(x0, w1, b1, m1, h1, H, W, H, W, 1);
        conv3x3_kernel<C, true><<<grid, blk>>>(h1, w2, b2, m1, h2, H, W, H, W, 1);
        conv3x3_kernel<C, true><<<grid, blk>>>(h2, w3, b3, m1, h1, H, W, H, W, 1);
    }
    // 7. mask4
    mask4_kernel<<<(BATCH * HT * HT + 255) / 256, 256>>>();
    // 8. conv transpose
    {
        dim3 grid((HT + 7) / 8, (HT + 7) / 8, BATCH), blk(16, 8);
        convT_kernel<<<grid, blk>>>(h1, wt, bt, m4, ht);
    }
    // 9. final VALID conv -> d_out
    {
        dim3 grid((HO + 7) / 8, (HO + 7) / 8, BATCH), blk(16, 8);
        conv3x3_kernel<C, false><<<grid, blk>>>(ht, w5, b5, nullptr, out,
                                                HT, HT, HO, HO, 0);
    }
}

// round 4
// speedup vs baseline: 1.9752x; 1.9752x over previous
#include <cuda_runtime.h>
#include <cstdint>

#define BATCH 4
#define H 256
#define W 256
#define C0 32
#define C 64
#define HT 513   // conv_transpose output spatial
#define HO 511   // final VALID conv output

// ---------------------------------------------------------------------------
// Scratch (static device memory; no cudaMalloc allowed)
// ---------------------------------------------------------------------------
__device__ float g_x0[BATCH * H * W * C0];
__device__ float g_mask0[BATCH * H * W];
__device__ float g_mask1[BATCH * H * W];
__device__ float g_mask4[BATCH * HT * HT];
__device__ float g_h1[BATCH * H * W * C];
__device__ float g_h2[BATCH * H * W * C];
__device__ float g_ht[BATCH * HT * HT * C];
__device__ float g_wT2[9 * 64 * 64];
__device__ float g_wT3[9 * 64 * 64];
__device__ float g_wT5[9 * 64 * 64];

// ---------------------------------------------------------------------------
// helpers
// ---------------------------------------------------------------------------
__device__ __forceinline__ uint32_t smem_u32(const void* p) {
    uint32_t a;
    asm("{ .reg .u64 t; cvta.to.shared.u64 t, %1; cvt.u32.u64 %0, t; }" : "=r"(a) : "l"(p));
    return a;
}
__device__ __forceinline__ float tf32r(float x) {
    float y;
    asm("cvt.rna.tf32.f32 %0, %1;" : "=f"(y) : "f"(x));
    return y;
}

// Branch selector only. Host pass (__CUDA_ARCH__ undefined) parses the tcgen05
// branch but never emits code for it; the compute_103 (non-'a') device pass
// takes the scalar fallback so its PTX contains no tcgen05.
#if defined(__CUDA_ARCH_FEAT_SM103_ALL) || defined(__CUDA_ARCH_FEAT_SM100_ALL) || !defined(__CUDA_ARCH__)
#define HAS_TCGEN05 1
#else
#define HAS_TCGEN05 0
#endif

// ---- macros defined unconditionally (text only; emitted only on sm_103a) ----
#define MBARRIER_INIT(a, c) \
    asm volatile("mbarrier.init.shared.b64 [%0], %1;" :: "r"(a), "r"(c) : "memory")
#define MBARRIER_WAIT_PARITY(a, ph) do { \
    uint32_t _m = (a), _p = (ph), _d; \
    asm volatile("{\n\t.reg .pred p;\n\t" \
        "mbarrier.try_wait.parity.acquire.cta.shared::cta.b64 p, [%1], %2;\n\t" \
        "selp.b32 %0, 1, 0, p;\n\t}" : "=r"(_d) : "r"(_m), "r"(_p) : "memory"); \
    if (!_d) { \
        asm volatile("{\n\t.reg .pred P1;\n\t" \
            "WL_%=:\n\t" \
            "mbarrier.try_wait.parity.acquire.cta.shared::cta.b64 P1, [%0], %1, 0x989680;\n\t" \
            "@P1 bra.uni WD_%=;\n\t" \
            "bra.uni WL_%=;\n\t" \
            "WD_%=:\n\t}" :: "r"(_m), "r"(_p) : "memory"); \
    } } while (0)

#define TCGEN05_ALLOC(dst, n) \
    asm volatile("tcgen05.alloc.cta_group::1.sync.aligned.shared::cta.b32 [%0], %1;" \
                 :: "r"(dst), "r"(n) : "memory")
#define TCGEN05_RELINQ() \
    asm volatile("tcgen05.relinquish_alloc_permit.cta_group::1.sync.aligned;")
#define TCGEN05_DEALLOC(t, n) \
    asm volatile("tcgen05.dealloc.cta_group::1.sync.aligned.b32 %0, %1;" :: "r"(t), "r"(n))
#define TCGEN05_COMMIT(mb) \
    asm volatile("tcgen05.commit.cta_group::1.mbarrier::arrive::one.shared::cluster.b64 [%0];" \
                 :: "r"(mb) : "memory")
#define TCGEN05_FENCE_AFTER() asm volatile("tcgen05.fence::after_thread_sync;" ::: "memory")
#define TCGEN05_FENCE_BEFORE() asm volatile("tcgen05.fence::before_thread_sync;" ::: "memory")
#define TCGEN05_WAIT_LD() asm volatile("tcgen05.wait::ld.sync.aligned;" ::: "memory")
#define FENCE_PROXY_ASYNC() asm volatile("fence.proxy.async.shared::cta;" ::: "memory")

#define TCGEN05_LD_X32(r, addr) \
    asm volatile("tcgen05.ld.sync.aligned.32x32b.x32.b32 " \
        "{%0,%1,%2,%3,%4,%5,%6,%7,%8,%9,%10,%11,%12,%13,%14,%15," \
        "%16,%17,%18,%19,%20,%21,%22,%23,%24,%25,%26,%27,%28,%29,%30,%31}, [%32];" \
        : "=r"((r)[0]), "=r"((r)[1]), "=r"((r)[2]), "=r"((r)[3]), \
          "=r"((r)[4]), "=r"((r)[5]), "=r"((r)[6]), "=r"((r)[7]), \
          "=r"((r)[8]), "=r"((r)[9]), "=r"((r)[10]), "=r"((r)[11]), \
          "=r"((r)[12]), "=r"((r)[13]), "=r"((r)[14]), "=r"((r)[15]), \
          "=r"((r)[16]), "=r"((r)[17]), "=r"((r)[18]), "=r"((r)[19]), \
          "=r"((r)[20]), "=r"((r)[21]), "=r"((r)[22]), "=r"((r)[23]), \
          "=r"((r)[24]), "=r"((r)[25]), "=r"((r)[26]), "=r"((r)[27]), \
          "=r"((r)[28]), "=r"((r)[29]), "=r"((r)[30]), "=r"((r)[31]) \
        : "r"(addr))

// idesc kind::tf32: dtype=F32(1<<4), atype=TF32(2<<7), btype=TF32(2<<10),
// N=64 ((64/8)<<17), M=128 ((128/16)<<24)
#define TF32_IDESC 0x8100910u

#define TC_MMA_TF32(dt, ad, bd, en) \
    asm volatile("{\n\t.reg .pred p;\n\tsetp.ne.u32 p, %4, 0;\n\t" \
        "tcgen05.mma.cta_group::1.kind::tf32 [%0], %1, %2, %3, p;\n\t}" \
        :: "r"(dt), "l"(ad), "l"(bd), "r"(TF32_IDESC), "r"(en) : "memory")

// SW128 descriptor: LBO=1, SBO=64, version=1, layout=SW128
#define DESC_BASE_SW128 \
    ((2ull << 61) | (1ull << 46) | (64ull << 32) | (1ull << 16))
#define MAKE_DESC(a) (DESC_BASE_SW128 | ((uint64_t)((a) >> 4) & 0x3FFF))

// ---------------------------------------------------------------------------
// Preprocess / scatter / mask kernels
// ---------------------------------------------------------------------------
__global__ void transposeW_kernel(const float* __restrict__ w, float* __restrict__ wT) {
    int i = blockIdx.x * blockDim.x + threadIdx.x;
    if (i >= 9 * 64 * 64) return;
    int co = i & 63, ci = (i >> 6) & 63, k = i >> 12;
    wT[(k * 64 + co) * 64 + ci] = w[(k * 64 + ci) * 64 + co];
}

__global__ void zero_kernel() {
    int i = blockIdx.x * blockDim.x + threadIdx.x;
    if (i < BATCH * H * W * C0 / 4)
        reinterpret_cast<float4*>(g_x0)[i] = make_float4(0.f, 0.f, 0.f, 0.f);
    if (i < BATCH * H * W / 4)
        reinterpret_cast<float4*>(g_mask0)[i] = make_float4(0.f, 0.f, 0.f, 0.f);
}

__global__ void scatter_kernel(const float* __restrict__ feat,
                               const int* __restrict__ coors, int n) {
    int t = blockIdx.x * blockDim.x + threadIdx.x;
    int p = t >> 5, c = t & 31;
    if (p >= n) return;
    int b = coors[3 * p + 0], y = coors[3 * p + 1], x = coors[3 * p + 2];
    int pix = (b * H + y) * W + x;
    atomicAdd(&g_x0[pix * C0 + c], feat[p * C0 + c]);
    if (c == 0) g_mask0[pix] = 1.0f;
}

__global__ void mask1_kernel() {
    int i = blockIdx.x * blockDim.x + threadIdx.x;
    if (i >= BATCH * H * W) return;
    int x = i % W, y = (i / W) % H, b = i / (H * W);
    float m = 0.f;
#pragma unroll
    for (int dy = -1; dy <= 1; dy++)
#pragma unroll
        for (int dx = -1; dx <= 1; dx++) {
            int yy = y + dy, xx = x + dx;
            if (yy >= 0 && yy < H && xx >= 0 && xx < W)
                m = fmaxf(m, g_mask0[(b * H + yy) * W + xx]);
        }
    g_mask1[i] = (m > 0.f) ? 1.f : 0.f;
}

__global__ void mask4_kernel() {
    int i = blockIdx.x * blockDim.x + threadIdx.x;
    if (i >= BATCH * HT * HT) return;
    int ox = i % HT, oy = (i / HT) % HT, b = i / (HT * HT);
    float m = 0.f;
#pragma unroll
    for (int ky = 0; ky < 3; ky++) {
        int t = oy + ky - 2;
        if (t & 1) continue;
        int iy = t >> 1;
        if (iy < 0 || iy >= H) continue;
#pragma unroll
        for (int kx = 0; kx < 3; kx++) {
            int s = ox + kx - 2;
            if (s & 1) continue;
            int ix = s >> 1;
            if (ix < 0 || ix >= W) continue;
            m = fmaxf(m, g_mask1[(b * H + iy) * W + ix]);
        }
    }
    g_mask4[i] = (m > 0.f) ? 1.f : 0.f;
}

// ---------------------------------------------------------------------------
// FFMA conv (kept for conv1, CIN=32)
// ---------------------------------------------------------------------------
template <int CIN, bool MASK>
__global__ __launch_bounds__(128)
void conv3x3_kernel(const float* __restrict__ in, const float* __restrict__ w,
                    const float* __restrict__ bias, const float* __restrict__ mask,
                    float* __restrict__ out,
                    int IH, int IW, int OH, int OW, int pad) {
    constexpr int ROWF = 10 * CIN + 4;
    __shared__ float smem[10 * ROWF];
    const int tx = threadIdx.x, ty = threadIdx.y;
    const int tid = ty * 16 + tx;
    const int oy0 = blockIdx.y * 8, ox0 = blockIdx.x * 8, b = blockIdx.z;
    const int iy0 = oy0 - pad, ix0 = ox0 - pad;
    const float* inb = in + (size_t)b * IH * IW * CIN;

    for (int i = tid; i < 10 * 10 * (CIN / 4); i += 128) {
        int ci4 = i % (CIN / 4);
        int pix = i / (CIN / 4);
        int r = pix / 10, cc = pix % 10;
        int iy = iy0 + r, ix = ix0 + cc;
        float4 v = make_float4(0.f, 0.f, 0.f, 0.f);
        if (iy >= 0 && iy < IH && ix >= 0 && ix < IW)
            v = *reinterpret_cast<const float4*>(inb + ((size_t)iy * IW + ix) * CIN + 4 * ci4);
        *reinterpret_cast<float4*>(&smem[r * ROWF + cc * CIN + 4 * ci4]) = v;
    }
    __syncthreads();

    float4 acc[8];
#pragma unroll
    for (int p = 0; p < 8; p++) acc[p] = make_float4(0.f, 0.f, 0.f, 0.f);

#pragma unroll 1
    for (int k = 0; k < 9; k++) {
        int ky = k / 3, kx = k - ky * 3;
        const float* wp = w + (size_t)k * CIN * 64 + 4 * tx;
        const float* sp = &smem[(ty + ky) * ROWF + kx * CIN];
#pragma unroll 8
        for (int ci = 0; ci < CIN; ci++) {
            float4 wv = *reinterpret_cast<const float4*>(wp + ci * 64);
#pragma unroll
            for (int p = 0; p < 8; p++) {
                float iv = sp[p * CIN + ci];
                acc[p].x = fmaf(iv, wv.x, acc[p].x);
                acc[p].y = fmaf(iv, wv.y, acc[p].y);
                acc[p].z = fmaf(iv, wv.z, acc[p].z);
                acc[p].w = fmaf(iv, wv.w, acc[p].w);
            }
        }
    }

    float4 bv = *reinterpret_cast<const float4*>(bias + 4 * tx);
    int oy = oy0 + ty;
    if (oy < OH) {
#pragma unroll
        for (int p = 0; p < 8; p++) {
            int ox = ox0 + p;
            if (ox < OW) {
                float4 v;
                v.x = acc[p].x + bv.x; v.y = acc[p].y + bv.y;
                v.z = acc[p].z + bv.z; v.w = acc[p].w + bv.w;
                if (MASK) {
                    float m = mask[((size_t)b * OH + oy) * OW + ox];
                    v.x *= m; v.y *= m; v.z *= m; v.w *= m;
                }
                v.x = fmaxf(v.x, 0.f); v.y = fmaxf(v.y, 0.f);
                v.z = fmaxf(v.z, 0.f); v.w = fmaxf(v.w, 0.f);
                *reinterpret_cast<float4*>(out + (((size_t)b * OH + oy) * OW + ox) * 64 + 4 * tx) = v;
            }
        }
    }
}

// ---------------------------------------------------------------------------
// conv_transpose (FFMA path)
// ---------------------------------------------------------------------------
__global__ __launch_bounds__(128)
void convT_kernel(const float* __restrict__ in, const float* __restrict__ w,
                  const float* __restrict__ bias, const float* __restrict__ mask,
                  float* __restrict__ out) {
    constexpr int IST = 6 * 64 + 4;
    __shared__ float smem[6 * IST];
    const int tx = threadIdx.x, ty = threadIdx.y;
    const int tid = ty * 16 + tx;
    const int oy0 = blockIdx.y * 8, ox0 = blockIdx.x * 8, b = blockIdx.z;
    const int iyb = oy0 / 2 - 1, ixb = ox0 / 2 - 1;
    const float* inb = in + (size_t)b * H * W * 64;

    for (int i = tid; i < 6 * 6 * 16; i += 128) {
        int ci4 = i & 15, pix = i >> 4;
        int r = pix / 6, cc = pix % 6;
        int iy = iyb + r, ix = ixb + cc;
        float4 v = make_float4(0.f, 0.f, 0.f, 0.f);
        if (iy >= 0 && iy < H && ix >= 0 && ix < W)
            v = *reinterpret_cast<const float4*>(inb + ((size_t)iy * W + ix) * 64 + 4 * ci4);
        *reinterpret_cast<float4*>(&smem[r * IST + cc * 64 + 4 * ci4]) = v;
    }
    __syncthreads();

    float4 acc[8];
#pragma unroll
    for (int p = 0; p < 8; p++) acc[p] = make_float4(0.f, 0.f, 0.f, 0.f);
    const int oy = oy0 + ty;

#pragma unroll 1
    for (int ky = 0; ky < 3; ky++) {
        if ((ty + ky) & 1) continue;
        const float* srow = &smem[((ty + ky) >> 1) * IST];
#pragma unroll
        for (int kx = 0; kx < 3; kx++) {
            const float* wp = w + (size_t)(ky * 3 + kx) * 64 * 64 + 4 * tx;
            const int p0 = kx & 1;
            const int col0 = (p0 + kx) >> 1;
#pragma unroll 8
            for (int ci = 0; ci < 64; ci++) {
                float4 wv = *reinterpret_cast<const float4*>(wp + ci * 64);
#pragma unroll
                for (int j = 0; j < 4; j++) {
                    float iv = srow[(col0 + j) * 64 + ci];
                    int p = p0 + 2 * j;
                    acc[p].x = fmaf(iv, wv.x, acc[p].x);
                    acc[p].y = fmaf(iv, wv.y, acc[p].y);
                    acc[p].z = fmaf(iv, wv.z, acc[p].z);
                    acc[p].w = fmaf(iv, wv.w, acc[p].w);
                }
            }
        }
    }

    float4 bv = *reinterpret_cast<const float4*>(bias + 4 * tx);
    if (oy < HT) {
#pragma unroll
        for (int p = 0; p < 8; p++) {
            int ox = ox0 + p;
            if (ox < HT) {
                float m = mask[((size_t)b * HT + oy) * HT + ox];
                float4 v;
                v.x = fmaxf((acc[p].x + bv.x) * m, 0.f);
                v.y = fmaxf((acc[p].y + bv.y) * m, 0.f);
                v.z = fmaxf((acc[p].z + bv.z) * m, 0.f);
                v.w = fmaxf((acc[p].w + bv.w) * m, 0.f);
                *reinterpret_cast<float4*>(out + (((size_t)b * HT + oy) * HT + ox) * 64 + 4 * tx) = v;
            }
        }
    }
}

// ---------------------------------------------------------------------------
// tcgen05 tf32 conv3x3, CIN=64, COUT=64 (sm_103a branch; scalar fallback for
// any non-'a' device pass keeps the PTX tcgen05-free there).
// ---------------------------------------------------------------------------
template <bool MASK>
__global__ __launch_bounds__(128)
void conv_tc_kernel(const float* __restrict__ in, const float* __restrict__ wT,
                    const float* __restrict__ bias, const float* __restrict__ mask,
                    float* __restrict__ out,
                    int IH, int IW, int OH, int OW, int pad) {
#if HAS_TCGEN05
    extern __shared__ char dsm[];
    __shared__ uint32_t s_tmem[1];
    __shared__ unsigned long long s_mbar;

    const int tid = threadIdx.x;
    const int wid = tid >> 5, lid = tid & 31;

    uint32_t dbase = smem_u32(dsm);
    uint32_t abase = (dbase + 1023u) & ~1023u;
    char* aptr = dsm + (abase - dbase);
    char* bptr = aptr + 32768;
    const uint32_t a_s = abase;
    const uint32_t b_s = abase + 32768;
    const uint32_t mbar = smem_u32(&s_mbar);

    if (wid == 0) {
        TCGEN05_ALLOC(smem_u32(&s_tmem[0]), 64);
        TCGEN05_RELINQ();
    }
    if (tid == 0) MBARRIER_INIT(mbar, 1);
    __syncthreads();
    const uint32_t tmem = s_tmem[0];

    const int x0 = blockIdx.x * 128;
    const int y = blockIdx.y;
    const int b = blockIdx.z;
    const float* inb = in + (size_t)b * IH * IW * 64;

    int phase = 0;
    bool first = true;

#pragma unroll 1
    for (int k = 0; k < 9; k++) {
        const int ky = k / 3, kx = k - ky * 3;
        const int row = y + ky - pad;
        if (row < 0 || row >= IH) continue;

        const float* rowp = inb + (size_t)row * IW * 64;
#pragma unroll
        for (int it = 0; it < 16; it++) {
            int i = tid + it * 128;
            int c4 = i & 15, m = i >> 4;
            int xin = x0 + m + kx - pad;
            float4 v = make_float4(0.f, 0.f, 0.f, 0.f);
            if (xin >= 0 && xin < IW)
                v = *reinterpret_cast<const float4*>(rowp + (size_t)xin * 64 + 4 * c4);
            v.x = tf32r(v.x); v.y = tf32r(v.y); v.z = tf32r(v.z); v.w = tf32r(v.w);
            int kk = 4 * c4;
            uint32_t off = ((uint32_t)(kk >> 5) * 16u + (uint32_t)(m >> 3)) * 1024u
                         + (uint32_t)(m & 7) * 128u + (uint32_t)(kk & 31) * 4u;
            off ^= (off >> 3) & 0x70u;
            *reinterpret_cast<float4*>(aptr + off) = v;
        }
        const float* wk = wT + k * 4096;
#pragma unroll
        for (int it = 0; it < 8; it++) {
            int i = tid + it * 128;
            int c4 = i & 15, n = i >> 4;
            float4 v = *reinterpret_cast<const float4*>(wk + (size_t)n * 64 + 4 * c4);
            v.x = tf32r(v.x); v.y = tf32r(v.y); v.z = tf32r(v.z); v.w = tf32r(v.w);
            int kk = 4 * c4;
            uint32_t off = ((uint32_t)(kk >> 5) * 8u + (uint32_t)(n >> 3)) * 1024u
                         + (uint32_t)(n & 7) * 128u + (uint32_t)(kk & 31) * 4u;
            off ^= (off >> 3) & 0x70u;
            *reinterpret_cast<float4*>(bptr + off) = v;
        }
        FENCE_PROXY_ASYNC();
        __syncthreads();

        if (tid == 0) {
            TCGEN05_FENCE_AFTER();
            uint64_t ad0 = MAKE_DESC(a_s);
            uint64_t bd0 = MAKE_DESC(b_s);
#pragma unroll
            for (int s = 0; s < 8; s++) {
                uint64_t ad = ad0 + (uint64_t)((s >> 2) * 1024 + (s & 3) * 2);
                uint64_t bd = bd0 + (uint64_t)((s >> 2) * 512 + (s & 3) * 2);
                unsigned en = (first && s == 0) ? 0u : 1u;
                TC_MMA_TF32(tmem, ad, bd, en);
            }
            TCGEN05_COMMIT(mbar);
        }
        first = false;
        MBARRIER_WAIT_PARITY(mbar, phase);
        phase ^= 1;
    }

    TCGEN05_FENCE_AFTER();

    uint32_t dreg[64];
    TCGEN05_LD_X32(dreg, tmem);
    TCGEN05_LD_X32(dreg + 32, tmem + 32);
    TCGEN05_WAIT_LD();
    TCGEN05_FENCE_BEFORE();

    const int m = wid * 32 + lid;
    const int ox = x0 + m;
    if (ox < OW) {
        float mval = 1.0f;
        if (MASK) mval = mask[((size_t)b * OH + y) * OW + ox];
        float* op = out + (((size_t)b * OH + y) * OW + ox) * 64;
#pragma unroll
        for (int c4 = 0; c4 < 16; c4++) {
            float4 bv = *reinterpret_cast<const float4*>(bias + 4 * c4);
            float4 v;
            v.x = fmaxf((__uint_as_float(dreg[4 * c4 + 0]) + bv.x) * mval, 0.f);
            v.y = fmaxf((__uint_as_float(dreg[4 * c4 + 1]) + bv.y) * mval, 0.f);
            v.z = fmaxf((__uint_as_float(dreg[4 * c4 + 2]) + bv.z) * mval, 0.f);
            v.w = fmaxf((__uint_as_float(dreg[4 * c4 + 3]) + bv.w) * mval, 0.f);
            *reinterpret_cast<float4*>(op + 4 * c4) = v;
        }
    }

    __syncthreads();
    if (wid == 0) TCGEN05_DEALLOC(tmem, 64);
#else
    // Correct scalar fallback (compute_103 pass only; never the fast path).
    const int tid = threadIdx.x;
    const int x0 = blockIdx.x * 128;
    const int y = blockIdx.y;
    const int b = blockIdx.z;
    const int ox = x0 + tid;
    if (ox >= OW) return;
    const float* inb = in + (size_t)b * IH * IW * 64;

    float acc[64];
#pragma unroll
    for (int c = 0; c < 64; c++) acc[c] = 0.f;

    for (int k = 0; k < 9; k++) {
        const int ky = k / 3, kx = k - ky * 3;
        const int row = y + ky - pad;
        const int col = ox + kx - pad;
        if (row < 0 || row >= IH || col < 0 || col >= IW) continue;
        const float* ip = inb + ((size_t)row * IW + col) * 64;
        const float* wk = wT + k * 4096;
        for (int ci = 0; ci < 64; ci++) {
            float iv = tf32r(ip[ci]);
#pragma unroll 16
            for (int co = 0; co < 64; co++)
                acc[co] = fmaf(iv, tf32r(wk[co * 64 + ci]), acc[co]);
        }
    }
    float mval = 1.0f;
    if (MASK) mval = mask[((size_t)b * OH + y) * OW + ox];
    float* op = out + (((size_t)b * OH + y) * OW + ox) * 64;
#pragma unroll
    for (int c = 0; c < 64; c++)
        op[c] = fmaxf((acc[c] + bias[c]) * mval, 0.f);
#endif
}

// ---------------------------------------------------------------------------
// Launch
// ---------------------------------------------------------------------------
extern "C" void kernel_launch(void* const* d_in, const int* in_sizes, int n_in,
                              void* d_out, int out_size) {
    const float* features = (const float*)d_in[0];
    const int* coors      = (const int*)d_in[1];
    const float* w1 = (const float*)d_in[3];
    const float* b1 = (const float*)d_in[4];
    const float* w2 = (const float*)d_in[5];
    const float* b2 = (const float*)d_in[6];
    const float* w3 = (const float*)d_in[7];
    const float* b3 = (const float*)d_in[8];
    const float* wt = (const float*)d_in[9];
    const float* bt = (const float*)d_in[10];
    const float* w5 = (const float*)d_in[11];
    const float* b5 = (const float*)d_in[12];
    float* out = (float*)d_out;

    const int N = in_sizes[0] / C0;

    float *x0, *m1, *m4, *h1, *h2, *ht, *wT2, *wT3, *wT5;
    cudaGetSymbolAddress((void**)&x0, g_x0);
    cudaGetSymbolAddress((void**)&m1, g_mask1);
    cudaGetSymbolAddress((void**)&m4, g_mask4);
    cudaGetSymbolAddress((void**)&h1, g_h1);
    cudaGetSymbolAddress((void**)&h2, g_h2);
    cudaGetSymbolAddress((void**)&ht, g_ht);
    cudaGetSymbolAddress((void**)&wT2, g_wT2);
    cudaGetSymbolAddress((void**)&wT3, g_wT3);
    cudaGetSymbolAddress((void**)&wT5, g_wT5);

    const int TC_SMEM = 1024 + 32768 + 16384;
    cudaFuncSetAttribute(conv_tc_kernel<true>,
                         cudaFuncAttributeMaxDynamicSharedMemorySize, TC_SMEM);
    cudaFuncSetAttribute(conv_tc_kernel<false>,
                         cudaFuncAttributeMaxDynamicSharedMemorySize, TC_SMEM);

    transposeW_kernel<<<(9 * 64 * 64 + 255) / 256, 256>>>(w2, wT2);
    transposeW_kernel<<<(9 * 64 * 64 + 255) / 256, 256>>>(w3, wT3);
    transposeW_kernel<<<(9 * 64 * 64 + 255) / 256, 256>>>(w5, wT5);

    {
        int n4 = BATCH * H * W * C0 / 4;
        zero_kernel<<<(n4 + 255) / 256, 256>>>();
    }
    scatter_kernel<<<(N * 32 + 255) / 256, 256>>>(features, coors, N);
    mask1_kernel<<<(BATCH * H * W + 255) / 256, 256>>>();

    {
        dim3 grid(W / 8, H / 8, BATCH), blk(16, 8);
        conv3x3_kernel<C0, true><<<grid, blk>>>(x0, w1, b1, m1, h1, H, W, H, W, 1);
    }
    {
        dim3 grid(W / 128, H, BATCH);
        conv_tc_kernel<true><<<grid, 128, TC_SMEM>>>(h1, wT2, b2, m1, h2, H, W, H, W, 1);
        conv_tc_kernel<true><<<grid, 128, TC_SMEM>>>(h2, wT3, b3, m1, h1, H, W, H, W, 1);
    }
    mask4_kernel<<<(BATCH * HT * HT + 255) / 256, 256>>>();
    {
        dim3 grid((HT + 7) / 8, (HT + 7) / 8, BATCH), blk(16, 8);
        convT_kernel<<<grid, blk>>>(h1, wt, bt, m4, ht);
    }
    {
        dim3 grid((HO + 127) / 128, HO, BATCH);
        conv_tc_kernel<false><<<grid, 128, TC_SMEM>>>(ht, wT5, b5, nullptr, out,
                                                      HT, HT, HO, HO, 0);
    }
}

// round 5
// speedup vs baseline: 3.4353x; 1.7393x over previous
#include <cuda_runtime.h>
#include <cstdint>

#define BATCH 4
#define H 256
#define W 256
#define C0 32
#define C 64
#define HT 513   // conv_transpose output spatial
#define HO 511   // final VALID conv output

// ---------------------------------------------------------------------------
// Scratch (static device memory; no cudaMalloc allowed)
// ---------------------------------------------------------------------------
__device__ float g_x0[BATCH * H * W * C0];
__device__ float g_mask0[BATCH * H * W];
__device__ float g_mask1[BATCH * H * W];
__device__ float g_mask4[BATCH * HT * HT];
__device__ float g_h1[BATCH * H * W * C];
__device__ float g_h2[BATCH * H * W * C];
__device__ float g_ht[BATCH * HT * HT * C];
__device__ float g_wT2[9 * 64 * 64];
__device__ float g_wT3[9 * 64 * 64];
__device__ float g_wT4[9 * 64 * 64];
__device__ float g_wT5[9 * 64 * 64];

// ---------------------------------------------------------------------------
// helpers
// ---------------------------------------------------------------------------
__device__ __forceinline__ uint32_t smem_u32(const void* p) {
    uint32_t a;
    asm("{ .reg .u64 t; cvta.to.shared.u64 t, %1; cvt.u32.u64 %0, t; }" : "=r"(a) : "l"(p));
    return a;
}
__device__ __forceinline__ float tf32r(float x) {
    float y;
    asm("cvt.rna.tf32.f32 %0, %1;" : "=f"(y) : "f"(x));
    return y;
}

// Branch selector: sm_103a (and sm_100a) device passes + host pass take the
// tcgen05 branch; the compute_103 (non-'a') device pass takes the scalar
// fallback so its PTX contains no tcgen05.
#if defined(__CUDA_ARCH_FEAT_SM103_ALL) || defined(__CUDA_ARCH_FEAT_SM100_ALL) || !defined(__CUDA_ARCH__)
#define HAS_TCGEN05 1
#else
#define HAS_TCGEN05 0
#endif

#define MBARRIER_INIT(a, c) \
    asm volatile("mbarrier.init.shared.b64 [%0], %1;" :: "r"(a), "r"(c) : "memory")
#define MBARRIER_WAIT_PARITY(a, ph) do { \
    uint32_t _m = (a), _p = (ph), _d; \
    asm volatile("{\n\t.reg .pred p;\n\t" \
        "mbarrier.try_wait.parity.acquire.cta.shared::cta.b64 p, [%1], %2;\n\t" \
        "selp.b32 %0, 1, 0, p;\n\t}" : "=r"(_d) : "r"(_m), "r"(_p) : "memory"); \
    if (!_d) { \
        asm volatile("{\n\t.reg .pred P1;\n\t" \
            "WL_%=:\n\t" \
            "mbarrier.try_wait.parity.acquire.cta.shared::cta.b64 P1, [%0], %1, 0x989680;\n\t" \
            "@P1 bra.uni WD_%=;\n\t" \
            "bra.uni WL_%=;\n\t" \
            "WD_%=:\n\t}" :: "r"(_m), "r"(_p) : "memory"); \
    } } while (0)

#define TCGEN05_ALLOC(dst, n) \
    asm volatile("tcgen05.alloc.cta_group::1.sync.aligned.shared::cta.b32 [%0], %1;" \
                 :: "r"(dst), "r"(n) : "memory")
#define TCGEN05_RELINQ() \
    asm volatile("tcgen05.relinquish_alloc_permit.cta_group::1.sync.aligned;")
#define TCGEN05_DEALLOC(t, n) \
    asm volatile("tcgen05.dealloc.cta_group::1.sync.aligned.b32 %0, %1;" :: "r"(t), "r"(n))
#define TCGEN05_COMMIT(mb) \
    asm volatile("tcgen05.commit.cta_group::1.mbarrier::arrive::one.shared::cluster.b64 [%0];" \
                 :: "r"(mb) : "memory")
#define TCGEN05_FENCE_AFTER() asm volatile("tcgen05.fence::after_thread_sync;" ::: "memory")
#define TCGEN05_FENCE_BEFORE() asm volatile("tcgen05.fence::before_thread_sync;" ::: "memory")
#define TCGEN05_WAIT_LD() asm volatile("tcgen05.wait::ld.sync.aligned;" ::: "memory")
#define FENCE_PROXY_ASYNC() asm volatile("fence.proxy.async.shared::cta;" ::: "memory")

#define TCGEN05_LD_X32(r, addr) \
    asm volatile("tcgen05.ld.sync.aligned.32x32b.x32.b32 " \
        "{%0,%1,%2,%3,%4,%5,%6,%7,%8,%9,%10,%11,%12,%13,%14,%15," \
        "%16,%17,%18,%19,%20,%21,%22,%23,%24,%25,%26,%27,%28,%29,%30,%31}, [%32];" \
        : "=r"((r)[0]), "=r"((r)[1]), "=r"((r)[2]), "=r"((r)[3]), \
          "=r"((r)[4]), "=r"((r)[5]), "=r"((r)[6]), "=r"((r)[7]), \
          "=r"((r)[8]), "=r"((r)[9]), "=r"((r)[10]), "=r"((r)[11]), \
          "=r"((r)[12]), "=r"((r)[13]), "=r"((r)[14]), "=r"((r)[15]), \
          "=r"((r)[16]), "=r"((r)[17]), "=r"((r)[18]), "=r"((r)[19]), \
          "=r"((r)[20]), "=r"((r)[21]), "=r"((r)[22]), "=r"((r)[23]), \
          "=r"((r)[24]), "=r"((r)[25]), "=r"((r)[26]), "=r"((r)[27]), \
          "=r"((r)[28]), "=r"((r)[29]), "=r"((r)[30]), "=r"((r)[31]) \
        : "r"(addr))

// idesc kind::tf32: dtype=F32(1<<4), atype=TF32(2<<7), btype=TF32(2<<10),
// N=64 ((64/8)<<17), M=128 ((128/16)<<24)
#define TF32_IDESC 0x8100910u

#define TC_MMA_TF32(dt, ad, bd, en) \
    asm volatile("{\n\t.reg .pred p;\n\tsetp.ne.u32 p, %4, 0;\n\t" \
        "tcgen05.mma.cta_group::1.kind::tf32 [%0], %1, %2, %3, p;\n\t}" \
        :: "r"(dt), "l"(ad), "l"(bd), "r"(TF32_IDESC), "r"(en) : "memory")

// SW128 descriptor: LBO=1, SBO=64, version=1, layout=SW128
#define DESC_BASE_SW128 \
    ((2ull << 61) | (1ull << 46) | (64ull << 32) | (1ull << 16))
#define MAKE_DESC(a) (DESC_BASE_SW128 | ((uint64_t)((a) >> 4) & 0x3FFF))

// ---------------------------------------------------------------------------
// Staging helpers (device-side, tcgen05 branch only)
// ---------------------------------------------------------------------------
// A: 128 pixels x 64 ch, SW128 blocked-atom (2 atom-cols of 16KB).
// B: 64 rows x 64 ch, SW128 blocked-atom (2 atom-cols of 8KB).
__device__ __forceinline__ void stage_A64(char* aptr, int tid,
                                          const float* __restrict__ rowp,
                                          int ixb, int iw_lim) {
#pragma unroll
    for (int it = 0; it < 16; it++) {
        int i = tid + it * 128;
        int c4 = i & 15, m = i >> 4;
        int ix = ixb + m;
        float4 v = make_float4(0.f, 0.f, 0.f, 0.f);
        if (ix >= 0 && ix < iw_lim)
            v = *reinterpret_cast<const float4*>(rowp + (size_t)ix * 64 + 4 * c4);
        v.x = tf32r(v.x); v.y = tf32r(v.y); v.z = tf32r(v.z); v.w = tf32r(v.w);
        int kk = 4 * c4;
        uint32_t off = ((uint32_t)(kk >> 5) * 16u + (uint32_t)(m >> 3)) * 1024u
                     + (uint32_t)(m & 7) * 128u + (uint32_t)(kk & 31) * 4u;
        off ^= (off >> 3) & 0x70u;
        *reinterpret_cast<float4*>(aptr + off) = v;
    }
}
__device__ __forceinline__ void stage_B64(char* bptr, int tid,
                                          const float* __restrict__ wk) {
#pragma unroll
    for (int it = 0; it < 8; it++) {
        int i = tid + it * 128;
        int c4 = i & 15, n = i >> 4;
        float4 v = *reinterpret_cast<const float4*>(wk + (size_t)n * 64 + 4 * c4);
        v.x = tf32r(v.x); v.y = tf32r(v.y); v.z = tf32r(v.z); v.w = tf32r(v.w);
        int kk = 4 * c4;
        uint32_t off = ((uint32_t)(kk >> 5) * 8u + (uint32_t)(n >> 3)) * 1024u
                     + (uint32_t)(n & 7) * 128u + (uint32_t)(kk & 31) * 4u;
        off ^= (off >> 3) & 0x70u;
        *reinterpret_cast<float4*>(bptr + off) = v;
    }
}

// ---------------------------------------------------------------------------
// Preprocess / scatter / mask kernels
// ---------------------------------------------------------------------------
__global__ void transposeW_kernel(const float* __restrict__ w, float* __restrict__ wT) {
    int i = blockIdx.x * blockDim.x + threadIdx.x;
    if (i >= 9 * 64 * 64) return;
    int co = i & 63, ci = (i >> 6) & 63, k = i >> 12;
    wT[(k * 64 + co) * 64 + ci] = w[(k * 64 + ci) * 64 + co];
}

__global__ void zero_kernel() {
    int i = blockIdx.x * blockDim.x + threadIdx.x;
    if (i < BATCH * H * W * C0 / 4)
        reinterpret_cast<float4*>(g_x0)[i] = make_float4(0.f, 0.f, 0.f, 0.f);
    if (i < BATCH * H * W / 4)
        reinterpret_cast<float4*>(g_mask0)[i] = make_float4(0.f, 0.f, 0.f, 0.f);
}

__global__ void scatter_kernel(const float* __restrict__ feat,
                               const int* __restrict__ coors, int n) {
    int t = blockIdx.x * blockDim.x + threadIdx.x;
    int p = t >> 5, c = t & 31;
    if (p >= n) return;
    int b = coors[3 * p + 0], y = coors[3 * p + 1], x = coors[3 * p + 2];
    int pix = (b * H + y) * W + x;
    atomicAdd(&g_x0[pix * C0 + c], feat[p * C0 + c]);
    if (c == 0) g_mask0[pix] = 1.0f;
}

__global__ void mask1_kernel() {
    int i = blockIdx.x * blockDim.x + threadIdx.x;
    if (i >= BATCH * H * W) return;
    int x = i % W, y = (i / W) % H, b = i / (H * W);
    float m = 0.f;
#pragma unroll
    for (int dy = -1; dy <= 1; dy++)
#pragma unroll
        for (int dx = -1; dx <= 1; dx++) {
            int yy = y + dy, xx = x + dx;
            if (yy >= 0 && yy < H && xx >= 0 && xx < W)
                m = fmaxf(m, g_mask0[(b * H + yy) * W + xx]);
        }
    g_mask1[i] = (m > 0.f) ? 1.f : 0.f;
}

__global__ void mask4_kernel() {
    int i = blockIdx.x * blockDim.x + threadIdx.x;
    if (i >= BATCH * HT * HT) return;
    int ox = i % HT, oy = (i / HT) % HT, b = i / (HT * HT);
    float m = 0.f;
#pragma unroll
    for (int ky = 0; ky < 3; ky++) {
        int t = oy + ky - 2;
        if (t & 1) continue;
        int iy = t >> 1;
        if (iy < 0 || iy >= H) continue;
#pragma unroll
        for (int kx = 0; kx < 3; kx++) {
            int s = ox + kx - 2;
            if (s & 1) continue;
            int ix = s >> 1;
            if (ix < 0 || ix >= W) continue;
            m = fmaxf(m, g_mask1[(b * H + iy) * W + ix]);
        }
    }
    g_mask4[i] = (m > 0.f) ? 1.f : 0.f;
}

// ---------------------------------------------------------------------------
// FFMA conv (conv1, CIN=32)
// ---------------------------------------------------------------------------
template <int CIN, bool MASK>
__global__ __launch_bounds__(128)
void conv3x3_kernel(const float* __restrict__ in, const float* __restrict__ w,
                    const float* __restrict__ bias, const float* __restrict__ mask,
                    float* __restrict__ out,
                    int IH, int IW, int OH, int OW, int pad) {
    constexpr int ROWF = 10 * CIN + 4;
    __shared__ float smem[10 * ROWF];
    const int tx = threadIdx.x, ty = threadIdx.y;
    const int tid = ty * 16 + tx;
    const int oy0 = blockIdx.y * 8, ox0 = blockIdx.x * 8, b = blockIdx.z;
    const int iy0 = oy0 - pad, ix0 = ox0 - pad;
    const float* inb = in + (size_t)b * IH * IW * CIN;

    for (int i = tid; i < 10 * 10 * (CIN / 4); i += 128) {
        int ci4 = i % (CIN / 4);
        int pix = i / (CIN / 4);
        int r = pix / 10, cc = pix % 10;
        int iy = iy0 + r, ix = ix0 + cc;
        float4 v = make_float4(0.f, 0.f, 0.f, 0.f);
        if (iy >= 0 && iy < IH && ix >= 0 && ix < IW)
            v = *reinterpret_cast<const float4*>(inb + ((size_t)iy * IW + ix) * CIN + 4 * ci4);
        *reinterpret_cast<float4*>(&smem[r * ROWF + cc * CIN + 4 * ci4]) = v;
    }
    __syncthreads();

    float4 acc[8];
#pragma unroll
    for (int p = 0; p < 8; p++) acc[p] = make_float4(0.f, 0.f, 0.f, 0.f);

#pragma unroll 1
    for (int k = 0; k < 9; k++) {
        int ky = k / 3, kx = k - ky * 3;
        const float* wp = w + (size_t)k * CIN * 64 + 4 * tx;
        const float* sp = &smem[(ty + ky) * ROWF + kx * CIN];
#pragma unroll 8
        for (int ci = 0; ci < CIN; ci++) {
            float4 wv = *reinterpret_cast<const float4*>(wp + ci * 64);
#pragma unroll
            for (int p = 0; p < 8; p++) {
                float iv = sp[p * CIN + ci];
                acc[p].x = fmaf(iv, wv.x, acc[p].x);
                acc[p].y = fmaf(iv, wv.y, acc[p].y);
                acc[p].z = fmaf(iv, wv.z, acc[p].z);
                acc[p].w = fmaf(iv, wv.w, acc[p].w);
            }
        }
    }

    float4 bv = *reinterpret_cast<const float4*>(bias + 4 * tx);
    int oy = oy0 + ty;
    if (oy < OH) {
#pragma unroll
        for (int p = 0; p < 8; p++) {
            int ox = ox0 + p;
            if (ox < OW) {
                float4 v;
                v.x = acc[p].x + bv.x; v.y = acc[p].y + bv.y;
                v.z = acc[p].z + bv.z; v.w = acc[p].w + bv.w;
                if (MASK) {
                    float m = mask[((size_t)b * OH + oy) * OW + ox];
                    v.x *= m; v.y *= m; v.z *= m; v.w *= m;
                }
                v.x = fmaxf(v.x, 0.f); v.y = fmaxf(v.y, 0.f);
                v.z = fmaxf(v.z, 0.f); v.w = fmaxf(v.w, 0.f);
                *reinterpret_cast<float4*>(out + (((size_t)b * OH + oy) * OW + ox) * 64 + 4 * tx) = v;
            }
        }
    }
}

// ---------------------------------------------------------------------------
// tcgen05 tf32 conv3x3, CIN=64, COUT=64
// ---------------------------------------------------------------------------
template <bool MASK>
__global__ __launch_bounds__(128)
void conv_tc_kernel(const float* __restrict__ in, const float* __restrict__ wT,
                    const float* __restrict__ bias, const float* __restrict__ mask,
                    float* __restrict__ out,
                    int IH, int IW, int OH, int OW, int pad) {
#if HAS_TCGEN05
    extern __shared__ char dsm[];
    __shared__ uint32_t s_tmem[1];
    __shared__ unsigned long long s_mbar;

    const int tid = threadIdx.x;
    const int wid = tid >> 5, lid = tid & 31;

    uint32_t dbase = smem_u32(dsm);
    uint32_t abase = (dbase + 1023u) & ~1023u;
    char* aptr = dsm + (abase - dbase);
    char* bptr = aptr + 32768;
    const uint32_t a_s = abase;
    const uint32_t b_s = abase + 32768;
    const uint32_t mbar = smem_u32(&s_mbar);

    if (wid == 0) {
        TCGEN05_ALLOC(smem_u32(&s_tmem[0]), 64);
        TCGEN05_RELINQ();
    }
    if (tid == 0) MBARRIER_INIT(mbar, 1);
    __syncthreads();
    const uint32_t tmem = s_tmem[0];

    const int x0 = blockIdx.x * 128;
    const int y = blockIdx.y;
    const int b = blockIdx.z;
    const float* inb = in + (size_t)b * IH * IW * 64;

    int phase = 0;
    bool first = true;

#pragma unroll 1
    for (int k = 0; k < 9; k++) {
        const int ky = k / 3, kx = k - ky * 3;
        const int row = y + ky - pad;
        if (row < 0 || row >= IH) continue;

        stage_A64(aptr, tid, inb + (size_t)row * IW * 64, x0 + kx - pad, IW);
        stage_B64(bptr, tid, wT + k * 4096);
        FENCE_PROXY_ASYNC();
        __syncthreads();

        if (tid == 0) {
            TCGEN05_FENCE_AFTER();
            uint64_t ad0 = MAKE_DESC(a_s);
            uint64_t bd0 = MAKE_DESC(b_s);
#pragma unroll
            for (int s = 0; s < 8; s++) {
                uint64_t ad = ad0 + (uint64_t)((s >> 2) * 1024 + (s & 3) * 2);
                uint64_t bd = bd0 + (uint64_t)((s >> 2) * 512 + (s & 3) * 2);
                unsigned en = (first && s == 0) ? 0u : 1u;
                TC_MMA_TF32(tmem, ad, bd, en);
            }
            TCGEN05_COMMIT(mbar);
        }
        first = false;
        MBARRIER_WAIT_PARITY(mbar, phase);
        phase ^= 1;
    }

    TCGEN05_FENCE_AFTER();

    uint32_t dreg[64];
    TCGEN05_LD_X32(dreg, tmem);
    TCGEN05_LD_X32(dreg + 32, tmem + 32);
    TCGEN05_WAIT_LD();
    TCGEN05_FENCE_BEFORE();

    const int m = wid * 32 + lid;
    const int ox = x0 + m;
    if (ox < OW) {
        float mval = 1.0f;
        if (MASK) mval = mask[((size_t)b * OH + y) * OW + ox];
        float* op = out + (((size_t)b * OH + y) * OW + ox) * 64;
#pragma unroll
        for (int c4 = 0; c4 < 16; c4++) {
            float4 bv = *reinterpret_cast<const float4*>(bias + 4 * c4);
            float4 v;
            v.x = fmaxf((__uint_as_float(dreg[4 * c4 + 0]) + bv.x) * mval, 0.f);
            v.y = fmaxf((__uint_as_float(dreg[4 * c4 + 1]) + bv.y) * mval, 0.f);
            v.z = fmaxf((__uint_as_float(dreg[4 * c4 + 2]) + bv.z) * mval, 0.f);
            v.w = fmaxf((__uint_as_float(dreg[4 * c4 + 3]) + bv.w) * mval, 0.f);
            *reinterpret_cast<float4*>(op + 4 * c4) = v;
        }
    }

    __syncthreads();
    if (wid == 0) TCGEN05_DEALLOC(tmem, 64);
#else
    // Correct scalar fallback (compute_103 pass only).
    const int tid = threadIdx.x;
    const int x0 = blockIdx.x * 128;
    const int y = blockIdx.y;
    const int b = blockIdx.z;
    const int ox = x0 + tid;
    if (ox >= OW) return;
    const float* inb = in + (size_t)b * IH * IW * 64;

    float acc[64];
#pragma unroll
    for (int c = 0; c < 64; c++) acc[c] = 0.f;

    for (int k = 0; k < 9; k++) {
        const int ky = k / 3, kx = k - ky * 3;
        const int row = y + ky - pad;
        const int col = ox + kx - pad;
        if (row < 0 || row >= IH || col < 0 || col >= IW) continue;
        const float* ip = inb + ((size_t)row * IW + col) * 64;
        const float* wk = wT + k * 4096;
        for (int ci = 0; ci < 64; ci++) {
            float iv = tf32r(ip[ci]);
#pragma unroll 16
            for (int co = 0; co < 64; co++)
                acc[co] = fmaf(iv, tf32r(wk[co * 64 + ci]), acc[co]);
        }
    }
    float mval = 1.0f;
    if (MASK) mval = mask[((size_t)b * OH + y) * OW + ox];
    float* op = out + (((size_t)b * OH + y) * OW + ox) * 64;
#pragma unroll
    for (int c = 0; c < 64; c++)
        op[c] = fmaxf((acc[c] + bias[c]) * mval, 0.f);
#endif
}

// ---------------------------------------------------------------------------
// tcgen05 tf32 conv_transpose 3x3 stride 2 VALID, parity-decomposed.
// Block handles 128 same-x-parity output pixels of one output row:
//   ox(m) = blockIdx.x*256 + cls + 2*m,  oy = blockIdx.y,  b/cls from z.
// Tap (ky,kx) active iff (oy+ky) and (cls+kx) are both even; then A rows are
// the contiguous input pixels ix(m) = (xbase+kx-2)/2 + m of row (oy+ky-2)/2.
// 1-4 GEMMs accumulated in TMEM; epilogue applies mask4/bias/relu at stride 2.
// ---------------------------------------------------------------------------
__global__ __launch_bounds__(128)
void convT_tc_kernel(const float* __restrict__ in, const float* __restrict__ wT,
                     const float* __restrict__ bias, const float* __restrict__ mask,
                     float* __restrict__ out) {
    const int cls = blockIdx.z & 1;
    const int b = blockIdx.z >> 1;
    const int oy = blockIdx.y;
    const int xbase = blockIdx.x * 256 + cls;
    if (xbase >= HT) return;
#if HAS_TCGEN05
    extern __shared__ char dsm[];
    __shared__ uint32_t s_tmem[1];
    __shared__ unsigned long long s_mbar;

    const int tid = threadIdx.x;
    const int wid = tid >> 5, lid = tid & 31;

    uint32_t dbase = smem_u32(dsm);
    uint32_t abase = (dbase + 1023u) & ~1023u;
    char* aptr = dsm + (abase - dbase);
    char* bptr = aptr + 32768;
    const uint32_t a_s = abase;
    const uint32_t b_s = abase + 32768;
    const uint32_t mbar = smem_u32(&s_mbar);

    if (wid == 0) {
        TCGEN05_ALLOC(smem_u32(&s_tmem[0]), 64);
        TCGEN05_RELINQ();
    }
    if (tid == 0) MBARRIER_INIT(mbar, 1);
    __syncthreads();
    const uint32_t tmem = s_tmem[0];

    const float* inb = in + (size_t)b * H * W * 64;

    int phase = 0;
    bool first = true;

#pragma unroll 1
    for (int ky = 0; ky < 3; ky++) {
        if ((oy + ky) & 1) continue;
        const int iy = (oy + ky - 2) >> 1;   // numerator even
        if (iy < 0 || iy >= H) continue;
        const float* rowp = inb + (size_t)iy * W * 64;
#pragma unroll 1
        for (int kx = 0; kx < 3; kx++) {
            if ((cls + kx) & 1) continue;
            const int ixb = (xbase + kx - 2) >> 1;  // numerator even

            stage_A64(aptr, tid, rowp, ixb, W);
            stage_B64(bptr, tid, wT + (ky * 3 + kx) * 4096);
            FENCE_PROXY_ASYNC();
            __syncthreads();

            if (tid == 0) {
                TCGEN05_FENCE_AFTER();
                uint64_t ad0 = MAKE_DESC(a_s);
                uint64_t bd0 = MAKE_DESC(b_s);
#pragma unroll
                for (int s = 0; s < 8; s++) {
                    uint64_t ad = ad0 + (uint64_t)((s >> 2) * 1024 + (s & 3) * 2);
                    uint64_t bd = bd0 + (uint64_t)((s >> 2) * 512 + (s & 3) * 2);
                    unsigned en = (first && s == 0) ? 0u : 1u;
                    TC_MMA_TF32(tmem, ad, bd, en);
                }
                TCGEN05_COMMIT(mbar);
            }
            first = false;
            MBARRIER_WAIT_PARITY(mbar, phase);
            phase ^= 1;
        }
    }

    TCGEN05_FENCE_AFTER();

    uint32_t dreg[64];
    TCGEN05_LD_X32(dreg, tmem);
    TCGEN05_LD_X32(dreg + 32, tmem + 32);
    TCGEN05_WAIT_LD();
    TCGEN05_FENCE_BEFORE();

    const int m = wid * 32 + lid;
    const int ox = xbase + 2 * m;
    if (ox < HT) {
        float mval = mask[((size_t)b * HT + oy) * HT + ox];
        float* op = out + (((size_t)b * HT + oy) * HT + ox) * 64;
#pragma unroll
        for (int c4 = 0; c4 < 16; c4++) {
            float4 bv = *reinterpret_cast<const float4*>(bias + 4 * c4);
            float4 v;
            v.x = fmaxf((__uint_as_float(dreg[4 * c4 + 0]) + bv.x) * mval, 0.f);
            v.y = fmaxf((__uint_as_float(dreg[4 * c4 + 1]) + bv.y) * mval, 0.f);
            v.z = fmaxf((__uint_as_float(dreg[4 * c4 + 2]) + bv.z) * mval, 0.f);
            v.w = fmaxf((__uint_as_float(dreg[4 * c4 + 3]) + bv.w) * mval, 0.f);
            *reinterpret_cast<float4*>(op + 4 * c4) = v;
        }
    }

    __syncthreads();
    if (wid == 0) TCGEN05_DEALLOC(tmem, 64);
#else
    // Correct scalar fallback (compute_103 pass only).
    const int tid = threadIdx.x;
    const int ox = xbase + 2 * tid;
    if (ox >= HT) return;
    const float* inb = in + (size_t)b * H * W * 64;

    float acc[64];
#pragma unroll
    for (int c = 0; c < 64; c++) acc[c] = 0.f;

    for (int ky = 0; ky < 3; ky++) {
        if ((oy + ky) & 1) continue;
        int iy = (oy + ky - 2) >> 1;
        if (iy < 0 || iy >= H) continue;
        for (int kx = 0; kx < 3; kx++) {
            if ((cls + kx) & 1) continue;
            int ix = (ox + kx - 2) >> 1;
            if (ix < 0 || ix >= W) continue;
            const float* ip = inb + ((size_t)iy * W + ix) * 64;
            const float* wk = wT + (ky * 3 + kx) * 4096;
            for (int ci = 0; ci < 64; ci++) {
                float iv = tf32r(ip[ci]);
#pragma unroll 16
                for (int co = 0; co < 64; co++)
                    acc[co] = fmaf(iv, tf32r(wk[co * 64 + ci]), acc[co]);
            }
        }
    }
    float mval = mask[((size_t)b * HT + oy) * HT + ox];
    float* op = out + (((size_t)b * HT + oy) * HT + ox) * 64;
#pragma unroll
    for (int c = 0; c < 64; c++)
        op[c] = fmaxf((acc[c] + bias[c]) * mval, 0.f);
#endif
}

// ---------------------------------------------------------------------------
// Launch
// ---------------------------------------------------------------------------
extern "C" void kernel_launch(void* const* d_in, const int* in_sizes, int n_in,
                              void* d_out, int out_size) {
    const float* features = (const float*)d_in[0];
    const int* coors      = (const int*)d_in[1];
    const float* w1 = (const float*)d_in[3];
    const float* b1 = (const float*)d_in[4];
    const float* w2 = (const float*)d_in[5];
    const float* b2 = (const float*)d_in[6];
    const float* w3 = (const float*)d_in[7];
    const float* b3 = (const float*)d_in[8];
    const float* wt = (const float*)d_in[9];
    const float* bt = (const float*)d_in[10];
    const float* w5 = (const float*)d_in[11];
    const float* b5 = (const float*)d_in[12];
    float* out = (float*)d_out;

    const int N = in_sizes[0] / C0;

    float *x0, *m1, *m4, *h1, *h2, *ht, *wT2, *wT3, *wT4, *wT5;
    cudaGetSymbolAddress((void**)&x0, g_x0);
    cudaGetSymbolAddress((void**)&m1, g_mask1);
    cudaGetSymbolAddress((void**)&m4, g_mask4);
    cudaGetSymbolAddress((void**)&h1, g_h1);
    cudaGetSymbolAddress((void**)&h2, g_h2);
    cudaGetSymbolAddress((void**)&ht, g_ht);
    cudaGetSymbolAddress((void**)&wT2, g_wT2);
    cudaGetSymbolAddress((void**)&wT3, g_wT3);
    cudaGetSymbolAddress((void**)&wT4, g_wT4);
    cudaGetSymbolAddress((void**)&wT5, g_wT5);

    const int TC_SMEM = 1024 + 32768 + 16384;
    cudaFuncSetAttribute(conv_tc_kernel<true>,
                         cudaFuncAttributeMaxDynamicSharedMemorySize, TC_SMEM);
    cudaFuncSetAttribute(conv_tc_kernel<false>,
                         cudaFuncAttributeMaxDynamicSharedMemorySize, TC_SMEM);
    cudaFuncSetAttribute(convT_tc_kernel,
                         cudaFuncAttributeMaxDynamicSharedMemorySize, TC_SMEM);

    transposeW_kernel<<<(9 * 64 * 64 + 255) / 256, 256>>>(w2, wT2);
    transposeW_kernel<<<(9 * 64 * 64 + 255) / 256, 256>>>(w3, wT3);
    transposeW_kernel<<<(9 * 64 * 64 + 255) / 256, 256>>>(wt, wT4);
    transposeW_kernel<<<(9 * 64 * 64 + 255) / 256, 256>>>(w5, wT5);

    {
        int n4 = BATCH * H * W * C0 / 4;
        zero_kernel<<<(n4 + 255) / 256, 256>>>();
    }
    scatter_kernel<<<(N * 32 + 255) / 256, 256>>>(features, coors, N);
    mask1_kernel<<<(BATCH * H * W + 255) / 256, 256>>>();

    {
        dim3 grid(W / 8, H / 8, BATCH), blk(16, 8);
        conv3x3_kernel<C0, true><<<grid, blk>>>(x0, w1, b1, m1, h1, H, W, H, W, 1);
    }
    {
        dim3 grid(W / 128, H, BATCH);
        conv_tc_kernel<true><<<grid, 128, TC_SMEM>>>(h1, wT2, b2, m1, h2, H, W, H, W, 1);
        conv_tc_kernel<true><<<grid, 128, TC_SMEM>>>(h2, wT3, b3, m1, h1, H, W, H, W, 1);
    }
    mask4_kernel<<<(BATCH * HT * HT + 255) / 256, 256>>>();
    {
        dim3 grid(3, HT, BATCH * 2);
        convT_tc_kernel<<<grid, 128, TC_SMEM>>>(h1, wT4, bt, m4, ht);
    }
    {
        dim3 grid((HO + 127) / 128, HO, BATCH);
        conv_tc_kernel<false><<<grid, 128, TC_SMEM>>>(ht, wT5, b5, nullptr, out,
                                                      HT, HT, HO, HO, 0);
    }
}

// round 6
// speedup vs baseline: 4.0164x; 1.1692x over previous
#include <cuda_runtime.h>
#include <cstdint>

#define BATCH 4
#define H 256
#define W 256
#define C0 32
#define C 64
#define HT 513   // conv_transpose output spatial
#define HO 511   // final VALID conv output

// ---------------------------------------------------------------------------
// Scratch (static device memory; no cudaMalloc allowed)
// ---------------------------------------------------------------------------
__device__ float g_x0[BATCH * H * W * C0];
__device__ float g_mask0[BATCH * H * W];
__device__ float g_mask1[BATCH * H * W];
__device__ float g_h1[BATCH * H * W * C];
__device__ float g_h2[BATCH * H * W * C];
__device__ float g_ht[BATCH * HT * HT * C];
__device__ float g_wT1[9 * 64 * 32];
__device__ float g_wT2[9 * 64 * 64];
__device__ float g_wT3[9 * 64 * 64];
__device__ float g_wT4[9 * 64 * 64];
__device__ float g_wT5[9 * 64 * 64];

// ---------------------------------------------------------------------------
// helpers
// ---------------------------------------------------------------------------
__device__ __forceinline__ uint32_t smem_u32(const void* p) {
    uint32_t a;
    asm("{ .reg .u64 t; cvta.to.shared.u64 t, %1; cvt.u32.u64 %0, t; }" : "=r"(a) : "l"(p));
    return a;
}
__device__ __forceinline__ float tf32r(float x) {
    float y;
    asm("cvt.rna.tf32.f32 %0, %1;" : "=f"(y) : "f"(x));
    return y;
}

// Branch selector: sm_103a/sm_100a device passes + host pass take the tcgen05
// branch; the compute_103 (non-'a') device pass takes the scalar fallback so
// its PTX contains no tcgen05.
#if defined(__CUDA_ARCH_FEAT_SM103_ALL) || defined(__CUDA_ARCH_FEAT_SM100_ALL) || !defined(__CUDA_ARCH__)
#define HAS_TCGEN05 1
#else
#define HAS_TCGEN05 0
#endif

#define MBARRIER_INIT(a, c) \
    asm volatile("mbarrier.init.shared.b64 [%0], %1;" :: "r"(a), "r"(c) : "memory")
#define MBARRIER_WAIT_PARITY(a, ph) do { \
    uint32_t _m = (a), _p = (ph), _d; \
    asm volatile("{\n\t.reg .pred p;\n\t" \
        "mbarrier.try_wait.parity.acquire.cta.shared::cta.b64 p, [%1], %2;\n\t" \
        "selp.b32 %0, 1, 0, p;\n\t}" : "=r"(_d) : "r"(_m), "r"(_p) : "memory"); \
    if (!_d) { \
        asm volatile("{\n\t.reg .pred P1;\n\t" \
            "WL_%=:\n\t" \
            "mbarrier.try_wait.parity.acquire.cta.shared::cta.b64 P1, [%0], %1, 0x989680;\n\t" \
            "@P1 bra.uni WD_%=;\n\t" \
            "bra.uni WL_%=;\n\t" \
            "WD_%=:\n\t}" :: "r"(_m), "r"(_p) : "memory"); \
    } } while (0)

#define TCGEN05_ALLOC(dst, n) \
    asm volatile("tcgen05.alloc.cta_group::1.sync.aligned.shared::cta.b32 [%0], %1;" \
                 :: "r"(dst), "r"(n) : "memory")
#define TCGEN05_RELINQ() \
    asm volatile("tcgen05.relinquish_alloc_permit.cta_group::1.sync.aligned;")
#define TCGEN05_DEALLOC(t, n) \
    asm volatile("tcgen05.dealloc.cta_group::1.sync.aligned.b32 %0, %1;" :: "r"(t), "r"(n))
#define TCGEN05_COMMIT(mb) \
    asm volatile("tcgen05.commit.cta_group::1.mbarrier::arrive::one.shared::cluster.b64 [%0];" \
                 :: "r"(mb) : "memory")
#define TCGEN05_FENCE_AFTER() asm volatile("tcgen05.fence::after_thread_sync;" ::: "memory")
#define TCGEN05_FENCE_BEFORE() asm volatile("tcgen05.fence::before_thread_sync;" ::: "memory")
#define TCGEN05_WAIT_LD() asm volatile("tcgen05.wait::ld.sync.aligned;" ::: "memory")
#define FENCE_PROXY_ASYNC() asm volatile("fence.proxy.async.shared::cta;" ::: "memory")

#define TCGEN05_LD_X32(r, addr) \
    asm volatile("tcgen05.ld.sync.aligned.32x32b.x32.b32 " \
        "{%0,%1,%2,%3,%4,%5,%6,%7,%8,%9,%10,%11,%12,%13,%14,%15," \
        "%16,%17,%18,%19,%20,%21,%22,%23,%24,%25,%26,%27,%28,%29,%30,%31}, [%32];" \
        : "=r"((r)[0]), "=r"((r)[1]), "=r"((r)[2]), "=r"((r)[3]), \
          "=r"((r)[4]), "=r"((r)[5]), "=r"((r)[6]), "=r"((r)[7]), \
          "=r"((r)[8]), "=r"((r)[9]), "=r"((r)[10]), "=r"((r)[11]), \
          "=r"((r)[12]), "=r"((r)[13]), "=r"((r)[14]), "=r"((r)[15]), \
          "=r"((r)[16]), "=r"((r)[17]), "=r"((r)[18]), "=r"((r)[19]), \
          "=r"((r)[20]), "=r"((r)[21]), "=r"((r)[22]), "=r"((r)[23]), \
          "=r"((r)[24]), "=r"((r)[25]), "=r"((r)[26]), "=r"((r)[27]), \
          "=r"((r)[28]), "=r"((r)[29]), "=r"((r)[30]), "=r"((r)[31]) \
        : "r"(addr))

// idesc kind::tf32: dtype=F32(1<<4), atype=TF32(2<<7), btype=TF32(2<<10),
// N=64 ((64/8)<<17), M=128 ((128/16)<<24)
#define TF32_IDESC 0x8100910u

#define TC_MMA_TF32(dt, ad, bd, en) \
    asm volatile("{\n\t.reg .pred p;\n\tsetp.ne.u32 p, %4, 0;\n\t" \
        "tcgen05.mma.cta_group::1.kind::tf32 [%0], %1, %2, %3, p;\n\t}" \
        :: "r"(dt), "l"(ad), "l"(bd), "r"(TF32_IDESC), "r"(en) : "memory")

// SW128 descriptor: LBO=1, SBO=64, version=1, layout=SW128
#define DESC_BASE_SW128 \
    ((2ull << 61) | (1ull << 46) | (64ull << 32) | (1ull << 16))
#define MAKE_DESC(a) (DESC_BASE_SW128 | ((uint64_t)((a) >> 4) & 0x3FFF))

// ---------------------------------------------------------------------------
// Staging helpers (tcgen05 branch). Layouts are SW128 blocked-atom; for
// CIN=64 the tile has 2 atom-columns, for CIN=32 a single atom-column
// (one 128B row per M-row).
// ---------------------------------------------------------------------------
__device__ __forceinline__ void stage_A64(char* aptr, int tid,
                                          const float* __restrict__ rowp,
                                          int ixb, int iw_lim) {
#pragma unroll
    for (int it = 0; it < 16; it++) {
        int i = tid + it * 128;
        int c4 = i & 15, m = i >> 4;
        int ix = ixb + m;
        float4 v = make_float4(0.f, 0.f, 0.f, 0.f);
        if (ix >= 0 && ix < iw_lim)
            v = *reinterpret_cast<const float4*>(rowp + (size_t)ix * 64 + 4 * c4);
        v.x = tf32r(v.x); v.y = tf32r(v.y); v.z = tf32r(v.z); v.w = tf32r(v.w);
        int kk = 4 * c4;
        uint32_t off = ((uint32_t)(kk >> 5) * 16u + (uint32_t)(m >> 3)) * 1024u
                     + (uint32_t)(m & 7) * 128u + (uint32_t)(kk & 31) * 4u;
        off ^= (off >> 3) & 0x70u;
        *reinterpret_cast<float4*>(aptr + off) = v;
    }
}
__device__ __forceinline__ void stage_B64(char* bptr, int tid,
                                          const float* __restrict__ wk) {
#pragma unroll
    for (int it = 0; it < 8; it++) {
        int i = tid + it * 128;
        int c4 = i & 15, n = i >> 4;
        float4 v = *reinterpret_cast<const float4*>(wk + (size_t)n * 64 + 4 * c4);
        v.x = tf32r(v.x); v.y = tf32r(v.y); v.z = tf32r(v.z); v.w = tf32r(v.w);
        int kk = 4 * c4;
        uint32_t off = ((uint32_t)(kk >> 5) * 8u + (uint32_t)(n >> 3)) * 1024u
                     + (uint32_t)(n & 7) * 128u + (uint32_t)(kk & 31) * 4u;
        off ^= (off >> 3) & 0x70u;
        *reinterpret_cast<float4*>(bptr + off) = v;
    }
}
// CIN=32: A = 128 px x 32 ch, one 128B row per pixel (16KB, 1 atom-col)
__device__ __forceinline__ void stage_A32(char* aptr, int tid,
                                          const float* __restrict__ rowp,
                                          int ixb, int iw_lim) {
#pragma unroll
    for (int it = 0; it < 8; it++) {
        int i = tid + it * 128;
        int c4 = i & 7, m = i >> 3;
        int ix = ixb + m;
        float4 v = make_float4(0.f, 0.f, 0.f, 0.f);
        if (ix >= 0 && ix < iw_lim)
            v = *reinterpret_cast<const float4*>(rowp + (size_t)ix * 32 + 4 * c4);
        v.x = tf32r(v.x); v.y = tf32r(v.y); v.z = tf32r(v.z); v.w = tf32r(v.w);
        uint32_t off = (uint32_t)m * 128u + (uint32_t)c4 * 16u;
        off ^= (off >> 3) & 0x70u;
        *reinterpret_cast<float4*>(aptr + off) = v;
    }
}
// B = 64 co x 32 ci (8KB, 1 atom-col)
__device__ __forceinline__ void stage_B32(char* bptr, int tid,
                                          const float* __restrict__ wk) {
#pragma unroll
    for (int it = 0; it < 4; it++) {
        int i = tid + it * 128;
        int c4 = i & 7, n = i >> 3;
        float4 v = *reinterpret_cast<const float4*>(wk + (size_t)n * 32 + 4 * c4);
        v.x = tf32r(v.x); v.y = tf32r(v.y); v.z = tf32r(v.z); v.w = tf32r(v.w);
        uint32_t off = (uint32_t)n * 128u + (uint32_t)c4 * 16u;
        off ^= (off >> 3) & 0x70u;
        *reinterpret_cast<float4*>(bptr + off) = v;
    }
}

// ---------------------------------------------------------------------------
// Preprocess / scatter / mask kernels
// ---------------------------------------------------------------------------
__global__ void transposeW_kernel(const float* __restrict__ w, float* __restrict__ wT) {
    int i = blockIdx.x * blockDim.x + threadIdx.x;
    if (i >= 9 * 64 * 64) return;
    int co = i & 63, ci = (i >> 6) & 63, k = i >> 12;
    wT[(k * 64 + co) * 64 + ci] = w[(k * 64 + ci) * 64 + co];
}
__global__ void transposeW1_kernel(const float* __restrict__ w, float* __restrict__ wT) {
    int i = blockIdx.x * blockDim.x + threadIdx.x;
    if (i >= 9 * 32 * 64) return;
    int co = i & 63, ci = (i >> 6) & 31, k = i >> 11;
    wT[(k * 64 + co) * 32 + ci] = w[(k * 32 + ci) * 64 + co];
}

__global__ void zero_kernel() {
    int i = blockIdx.x * blockDim.x + threadIdx.x;
    if (i < BATCH * H * W * C0 / 4)
        reinterpret_cast<float4*>(g_x0)[i] = make_float4(0.f, 0.f, 0.f, 0.f);
    if (i < BATCH * H * W / 4)
        reinterpret_cast<float4*>(g_mask0)[i] = make_float4(0.f, 0.f, 0.f, 0.f);
}

__global__ void scatter_kernel(const float* __restrict__ feat,
                               const int* __restrict__ coors, int n) {
    int t = blockIdx.x * blockDim.x + threadIdx.x;
    int p = t >> 5, c = t & 31;
    if (p >= n) return;
    int b = coors[3 * p + 0], y = coors[3 * p + 1], x = coors[3 * p + 2];
    int pix = (b * H + y) * W + x;
    atomicAdd(&g_x0[pix * C0 + c], feat[p * C0 + c]);
    if (c == 0) g_mask0[pix] = 1.0f;
}

__global__ void mask1_kernel() {
    int i = blockIdx.x * blockDim.x + threadIdx.x;
    if (i >= BATCH * H * W) return;
    int x = i % W, y = (i / W) % H, b = i / (H * W);
    float m = 0.f;
#pragma unroll
    for (int dy = -1; dy <= 1; dy++)
#pragma unroll
        for (int dx = -1; dx <= 1; dx++) {
            int yy = y + dy, xx = x + dx;
            if (yy >= 0 && yy < H && xx >= 0 && xx < W)
                m = fmaxf(m, g_mask0[(b * H + yy) * W + xx]);
        }
    g_mask1[i] = (m > 0.f) ? 1.f : 0.f;
}

// ---------------------------------------------------------------------------
// tcgen05 tf32 conv3x3, CIN templated (32 or 64), COUT=64
// ---------------------------------------------------------------------------
template <int CIN, bool MASK>
__global__ __launch_bounds__(128)
void conv_tc_kernel(const float* __restrict__ in, const float* __restrict__ wT,
                    const float* __restrict__ bias, const float* __restrict__ mask,
                    float* __restrict__ out,
                    int IH, int IW, int OH, int OW, int pad) {
#if HAS_TCGEN05
    extern __shared__ char dsm[];
    __shared__ uint32_t s_tmem[1];
    __shared__ unsigned long long s_mbar;

    const int tid = threadIdx.x;
    const int wid = tid >> 5, lid = tid & 31;

    constexpr int ABYTES = (CIN == 64) ? 32768 : 16384;
    constexpr int NSTEP = CIN / 8;            // MMA K-steps per tap
    uint32_t dbase = smem_u32(dsm);
    uint32_t abase = (dbase + 1023u) & ~1023u;
    char* aptr = dsm + (abase - dbase);
    char* bptr = aptr + ABYTES;
    const uint32_t a_s = abase;
    const uint32_t b_s = abase + ABYTES;
    const uint32_t mbar = smem_u32(&s_mbar);

    if (wid == 0) {
        TCGEN05_ALLOC(smem_u32(&s_tmem[0]), 64);
        TCGEN05_RELINQ();
    }
    if (tid == 0) MBARRIER_INIT(mbar, 1);
    __syncthreads();
    const uint32_t tmem = s_tmem[0];

    const int x0 = blockIdx.x * 128;
    const int y = blockIdx.y;
    const int b = blockIdx.z;
    const float* inb = in + (size_t)b * IH * IW * CIN;

    int phase = 0;
    bool first = true;

#pragma unroll 1
    for (int k = 0; k < 9; k++) {
        const int ky = k / 3, kx = k - ky * 3;
        const int row = y + ky - pad;
        if (row < 0 || row >= IH) continue;

        if (CIN == 64) {
            stage_A64(aptr, tid, inb + (size_t)row * IW * 64, x0 + kx - pad, IW);
            stage_B64(bptr, tid, wT + k * 4096);
        } else {
            stage_A32(aptr, tid, inb + (size_t)row * IW * 32, x0 + kx - pad, IW);
            stage_B32(bptr, tid, wT + k * 2048);
        }
        FENCE_PROXY_ASYNC();
        __syncthreads();

        if (tid == 0) {
            TCGEN05_FENCE_AFTER();
            uint64_t ad0 = MAKE_DESC(a_s);
            uint64_t bd0 = MAKE_DESC(b_s);
#pragma unroll
            for (int s = 0; s < NSTEP; s++) {
                uint64_t ad, bd;
                if (CIN == 64) {
                    ad = ad0 + (uint64_t)((s >> 2) * 1024 + (s & 3) * 2);
                    bd = bd0 + (uint64_t)((s >> 2) * 512 + (s & 3) * 2);
                } else {
                    ad = ad0 + (uint64_t)(s * 2);
                    bd = bd0 + (uint64_t)(s * 2);
                }
                unsigned en = (first && s == 0) ? 0u : 1u;
                TC_MMA_TF32(tmem, ad, bd, en);
            }
            TCGEN05_COMMIT(mbar);
        }
        first = false;
        MBARRIER_WAIT_PARITY(mbar, phase);
        phase ^= 1;
    }

    TCGEN05_FENCE_AFTER();

    uint32_t dreg[64];
    TCGEN05_LD_X32(dreg, tmem);
    TCGEN05_LD_X32(dreg + 32, tmem + 32);
    TCGEN05_WAIT_LD();
    TCGEN05_FENCE_BEFORE();

    const int m = wid * 32 + lid;
    const int ox = x0 + m;
    if (ox < OW) {
        float mval = 1.0f;
        if (MASK) mval = mask[((size_t)b * OH + y) * OW + ox];
        float* op = out + (((size_t)b * OH + y) * OW + ox) * 64;
#pragma unroll
        for (int c4 = 0; c4 < 16; c4++) {
            float4 bv = *reinterpret_cast<const float4*>(bias + 4 * c4);
            float4 v;
            v.x = fmaxf((__uint_as_float(dreg[4 * c4 + 0]) + bv.x) * mval, 0.f);
            v.y = fmaxf((__uint_as_float(dreg[4 * c4 + 1]) + bv.y) * mval, 0.f);
            v.z = fmaxf((__uint_as_float(dreg[4 * c4 + 2]) + bv.z) * mval, 0.f);
            v.w = fmaxf((__uint_as_float(dreg[4 * c4 + 3]) + bv.w) * mval, 0.f);
            *reinterpret_cast<float4*>(op + 4 * c4) = v;
        }
    }

    __syncthreads();
    if (wid == 0) TCGEN05_DEALLOC(tmem, 64);
#else
    // Correct scalar fallback (compute_103 pass only).
    const int tid = threadIdx.x;
    const int x0 = blockIdx.x * 128;
    const int y = blockIdx.y;
    const int b = blockIdx.z;
    const int ox = x0 + tid;
    if (ox >= OW) return;
    const float* inb = in + (size_t)b * IH * IW * CIN;

    float acc[64];
#pragma unroll
    for (int c = 0; c < 64; c++) acc[c] = 0.f;

    for (int k = 0; k < 9; k++) {
        const int ky = k / 3, kx = k - ky * 3;
        const int row = y + ky - pad;
        const int col = ox + kx - pad;
        if (row < 0 || row >= IH || col < 0 || col >= IW) continue;
        const float* ip = inb + ((size_t)row * IW + col) * CIN;
        const float* wk = wT + k * 64 * CIN;
        for (int ci = 0; ci < CIN; ci++) {
            float iv = tf32r(ip[ci]);
#pragma unroll 16
            for (int co = 0; co < 64; co++)
                acc[co] = fmaf(iv, tf32r(wk[co * CIN + ci]), acc[co]);
        }
    }
    float mval = 1.0f;
    if (MASK) mval = mask[((size_t)b * OH + y) * OW + ox];
    float* op = out + (((size_t)b * OH + y) * OW + ox) * 64;
#pragma unroll
    for (int c = 0; c < 64; c++)
        op[c] = fmaxf((acc[c] + bias[c]) * mval, 0.f);
#endif
}

// ---------------------------------------------------------------------------
// tcgen05 tf32 conv_transpose 3x3 stride 2 VALID, parity-decomposed, with
// mask4 computed inline from mask1 in the epilogue (mask4 kernel removed).
// ---------------------------------------------------------------------------
__global__ __launch_bounds__(128)
void convT_tc_kernel(const float* __restrict__ in, const float* __restrict__ wT,
                     const float* __restrict__ bias, const float* __restrict__ mask1,
                     float* __restrict__ out) {
    const int cls = blockIdx.z & 1;
    const int b = blockIdx.z >> 1;
    const int oy = blockIdx.y;
    const int xbase = blockIdx.x * 256 + cls;
    if (xbase >= HT) return;
#if HAS_TCGEN05
    extern __shared__ char dsm[];
    __shared__ uint32_t s_tmem[1];
    __shared__ unsigned long long s_mbar;

    const int tid = threadIdx.x;
    const int wid = tid >> 5, lid = tid & 31;

    uint32_t dbase = smem_u32(dsm);
    uint32_t abase = (dbase + 1023u) & ~1023u;
    char* aptr = dsm + (abase - dbase);
    char* bptr = aptr + 32768;
    const uint32_t a_s = abase;
    const uint32_t b_s = abase + 32768;
    const uint32_t mbar = smem_u32(&s_mbar);

    if (wid == 0) {
        TCGEN05_ALLOC(smem_u32(&s_tmem[0]), 64);
        TCGEN05_RELINQ();
    }
    if (tid == 0) MBARRIER_INIT(mbar, 1);
    __syncthreads();
    const uint32_t tmem = s_tmem[0];

    const float* inb = in + (size_t)b * H * W * 64;
    const float* m1b = mask1 + (size_t)b * H * W;

    int phase = 0;
    bool first = true;

#pragma unroll 1
    for (int ky = 0; ky < 3; ky++) {
        if ((oy + ky) & 1) continue;
        const int iy = (oy + ky - 2) >> 1;
        if (iy < 0 || iy >= H) continue;
        const float* rowp = inb + (size_t)iy * W * 64;
#pragma unroll 1
        for (int kx = 0; kx < 3; kx++) {
            if ((cls + kx) & 1) continue;
            const int ixb = (xbase + kx - 2) >> 1;

            stage_A64(aptr, tid, rowp, ixb, W);
            stage_B64(bptr, tid, wT + (ky * 3 + kx) * 4096);
            FENCE_PROXY_ASYNC();
            __syncthreads();

            if (tid == 0) {
                TCGEN05_FENCE_AFTER();
                uint64_t ad0 = MAKE_DESC(a_s);
                uint64_t bd0 = MAKE_DESC(b_s);
#pragma unroll
                for (int s = 0; s < 8; s++) {
                    uint64_t ad = ad0 + (uint64_t)((s >> 2) * 1024 + (s & 3) * 2);
                    uint64_t bd = bd0 + (uint64_t)((s >> 2) * 512 + (s & 3) * 2);
                    unsigned en = (first && s == 0) ? 0u : 1u;
                    TC_MMA_TF32(tmem, ad, bd, en);
                }
                TCGEN05_COMMIT(mbar);
            }
            first = false;
            MBARRIER_WAIT_PARITY(mbar, phase);
            phase ^= 1;
        }
    }

    TCGEN05_FENCE_AFTER();

    uint32_t dreg[64];
    TCGEN05_LD_X32(dreg, tmem);
    TCGEN05_LD_X32(dreg + 32, tmem + 32);
    TCGEN05_WAIT_LD();
    TCGEN05_FENCE_BEFORE();

    const int m = wid * 32 + lid;
    const int ox = xbase + 2 * m;
    if (ox < HT) {
        // inline mask4: OR of mask1 over the active tap set
        float mval = 0.f;
#pragma unroll
        for (int ky = 0; ky < 3; ky++) {
            if ((oy + ky) & 1) continue;
            int iy = (oy + ky - 2) >> 1;
            if (iy < 0 || iy >= H) continue;
#pragma unroll
            for (int kx = 0; kx < 3; kx++) {
                if ((cls + kx) & 1) continue;
                int ix = (ox + kx - 2) >> 1;
                if (ix >= 0 && ix < W)
                    mval = fmaxf(mval, m1b[(size_t)iy * W + ix]);
            }
        }
        mval = (mval > 0.f) ? 1.f : 0.f;

        float* op = out + (((size_t)b * HT + oy) * HT + ox) * 64;
#pragma unroll
        for (int c4 = 0; c4 < 16; c4++) {
            float4 bv = *reinterpret_cast<const float4*>(bias + 4 * c4);
            float4 v;
            v.x = fmaxf((__uint_as_float(dreg[4 * c4 + 0]) + bv.x) * mval, 0.f);
            v.y = fmaxf((__uint_as_float(dreg[4 * c4 + 1]) + bv.y) * mval, 0.f);
            v.z = fmaxf((__uint_as_float(dreg[4 * c4 + 2]) + bv.z) * mval, 0.f);
            v.w = fmaxf((__uint_as_float(dreg[4 * c4 + 3]) + bv.w) * mval, 0.f);
            *reinterpret_cast<float4*>(op + 4 * c4) = v;
        }
    }

    __syncthreads();
    if (wid == 0) TCGEN05_DEALLOC(tmem, 64);
#else
    // Correct scalar fallback (compute_103 pass only).
    const int tid = threadIdx.x;
    const int ox = xbase + 2 * tid;
    if (ox >= HT) return;
    const float* inb = in + (size_t)b * H * W * 64;
    const float* m1b = mask1 + (size_t)b * H * W;

    float acc[64];
#pragma unroll
    for (int c = 0; c < 64; c++) acc[c] = 0.f;
    float mval = 0.f;

    for (int ky = 0; ky < 3; ky++) {
        if ((oy + ky) & 1) continue;
        int iy = (oy + ky - 2) >> 1;
        if (iy < 0 || iy >= H) continue;
        for (int kx = 0; kx < 3; kx++) {
            if ((cls + kx) & 1) continue;
            int ix = (ox + kx - 2) >> 1;
            if (ix < 0 || ix >= W) continue;
            mval = fmaxf(mval, m1b[(size_t)iy * W + ix]);
            const float* ip = inb + ((size_t)iy * W + ix) * 64;
            const float* wk = wT + (ky * 3 + kx) * 4096;
            for (int ci = 0; ci < 64; ci++) {
                float iv = tf32r(ip[ci]);
#pragma unroll 16
                for (int co = 0; co < 64; co++)
                    acc[co] = fmaf(iv, tf32r(wk[co * 64 + ci]), acc[co]);
            }
        }
    }
    mval = (mval > 0.f) ? 1.f : 0.f;
    float* op = out + (((size_t)b * HT + oy) * HT + ox) * 64;
#pragma unroll
    for (int c = 0; c < 64; c++)
        op[c] = fmaxf((acc[c] + bias[c]) * mval, 0.f);
#endif
}

// ---------------------------------------------------------------------------
// Launch
// ---------------------------------------------------------------------------
extern "C" void kernel_launch(void* const* d_in, const int* in_sizes, int n_in,
                              void* d_out, int out_size) {
    const float* features = (const float*)d_in[0];
    const int* coors      = (const int*)d_in[1];
    const float* w1 = (const float*)d_in[3];
    const float* b1 = (const float*)d_in[4];
    const float* w2 = (const float*)d_in[5];
    const float* b2 = (const float*)d_in[6];
    const float* w3 = (const float*)d_in[7];
    const float* b3 = (const float*)d_in[8];
    const float* wt = (const float*)d_in[9];
    const float* bt = (const float*)d_in[10];
    const float* w5 = (const float*)d_in[11];
    const float* b5 = (const float*)d_in[12];
    float* out = (float*)d_out;

    const int N = in_sizes[0] / C0;

    float *x0, *m1, *h1, *h2, *ht, *wT1, *wT2, *wT3, *wT4, *wT5;
    cudaGetSymbolAddress((void**)&x0, g_x0);
    cudaGetSymbolAddress((void**)&m1, g_mask1);
    cudaGetSymbolAddress((void**)&h1, g_h1);
    cudaGetSymbolAddress((void**)&h2, g_h2);
    cudaGetSymbolAddress((void**)&ht, g_ht);
    cudaGetSymbolAddress((void**)&wT1, g_wT1);
    cudaGetSymbolAddress((void**)&wT2, g_wT2);
    cudaGetSymbolAddress((void**)&wT3, g_wT3);
    cudaGetSymbolAddress((void**)&wT4, g_wT4);
    cudaGetSymbolAddress((void**)&wT5, g_wT5);

    const int TC_SMEM64 = 1024 + 32768 + 16384;
    const int TC_SMEM32 = 1024 + 16384 + 8192;
    cudaFuncSetAttribute(conv_tc_kernel<64, true>,
                         cudaFuncAttributeMaxDynamicSharedMemorySize, TC_SMEM64);
    cudaFuncSetAttribute(conv_tc_kernel<64, false>,
                         cudaFuncAttributeMaxDynamicSharedMemorySize, TC_SMEM64);
    cudaFuncSetAttribute(conv_tc_kernel<32, true>,
                         cudaFuncAttributeMaxDynamicSharedMemorySize, TC_SMEM32);
    cudaFuncSetAttribute(convT_tc_kernel,
                         cudaFuncAttributeMaxDynamicSharedMemorySize, TC_SMEM64);

    transposeW1_kernel<<<(9 * 32 * 64 + 255) / 256, 256>>>(w1, wT1);
    transposeW_kernel<<<(9 * 64 * 64 + 255) / 256, 256>>>(w2, wT2);
    transposeW_kernel<<<(9 * 64 * 64 + 255) / 256, 256>>>(w3, wT3);
    transposeW_kernel<<<(9 * 64 * 64 + 255) / 256, 256>>>(wt, wT4);
    transposeW_kernel<<<(9 * 64 * 64 + 255) / 256, 256>>>(w5, wT5);

    {
        int n4 = BATCH * H * W * C0 / 4;
        zero_kernel<<<(n4 + 255) / 256, 256>>>();
    }
    scatter_kernel<<<(N * 32 + 255) / 256, 256>>>(features, coors, N);
    mask1_kernel<<<(BATCH * H * W + 255) / 256, 256>>>();

    {
        dim3 grid(W / 128, H, BATCH);
        conv_tc_kernel<32, true><<<grid, 128, TC_SMEM32>>>(x0, wT1, b1, m1, h1, H, W, H, W, 1);
        conv_tc_kernel<64, true><<<grid, 128, TC_SMEM64>>>(h1, wT2, b2, m1, h2, H, W, H, W, 1);
        conv_tc_kernel<64, true><<<grid, 128, TC_SMEM64>>>(h2, wT3, b3, m1, h1, H, W, H, W, 1);
    }
    {
        dim3 grid(3, HT, BATCH * 2);
        convT_tc_kernel<<<grid, 128, TC_SMEM64>>>(h1, wT4, bt, m1, ht);
    }
    {
        dim3 grid((HO + 127) / 128, HO, BATCH);
        conv_tc_kernel<64, false><<<grid, 128, TC_SMEM64>>>(ht, wT5, b5, nullptr, out,
                                                            HT, HT, HO, HO, 0);
    }
}